// round 14
// baseline (speedup 1.0000x reference)
#include <cuda_runtime.h>
#include <cuda_fp16.h>
#include <math.h>
#include <stdint.h>

#define NB 16

// ---------------- device scratch ----------------
__device__ float g_sum4[NB*2048];
__device__ float g_M3[NB*1024*9];
__device__ float g_M2[NB*512*49];
__device__ float g_A4[NB*2048];
__device__ float g_A3[NB*1024*9];
__device__ float g_A2[NB*512*49];
__device__ float g_CY[NB*512*49];
__device__ float g_down4[NB*512];
__device__ float g_cam4[NB*512];
__device__ float g_cam3[NB*512];
__device__ float g_cam2[NB*512];
__device__ float g_SGz[NB*512*9];

// fp16 hi/lo splits
__device__ __half g_h2[(size_t)NB*512*4096];
__device__ __half g_l2[(size_t)NB*512*4096];
__device__ __half g_h3[(size_t)NB*1024*1024];
__device__ __half g_l3[(size_t)NB*1024*1024];
__device__ __half g_h4[(size_t)NB*2048*256];
__device__ __half g_l4[(size_t)NB*2048*256];
// Gram scratch: only L2 materializes E
__device__ float g_E2[(size_t)NB*512*512];
// fused-softmax partials: L4 (K=1, NT=16) and L3 (K=9, NT=8)
__device__ float g_P4m[NB*16*2048];
__device__ float g_P4s[NB*16*2048];
__device__ float g_P4o[NB*16*2048];
__device__ float g_P3m[NB*8*1024];
__device__ float g_P3s[NB*8*1024];
__device__ float g_P3o[NB*8*1024*9];

__device__ __forceinline__ float warp_sum(float v){
#pragma unroll
  for(int o=16;o;o>>=1) v += __shfl_xor_sync(0xffffffffu, v, o);
  return v;
}

// ================= PTX helpers =================
__device__ __forceinline__ uint32_t s2u(const void* p){
  uint32_t a; asm("{ .reg .u64 t; cvta.to.shared.u64 t, %1; cvt.u32.u64 %0, t; }":"=r"(a):"l"(p));
  return a;
}
__device__ __forceinline__ void cp16(uint32_t d, const void* s){
  asm volatile("cp.async.cg.shared.global [%0], [%1], 16;\n"
               :: "r"(d), "l"(__cvta_generic_to_global(s)));
}
__device__ __forceinline__ void cp_commit(){ asm volatile("cp.async.commit_group;\n"); }
template<int N> __device__ __forceinline__ void cp_wait(){ asm volatile("cp.async.wait_group %0;\n"::"n"(N)); }

__device__ __forceinline__ void ldmx4(uint32_t* r, uint32_t addr){
  asm volatile("ldmatrix.sync.aligned.m8n8.x4.shared.b16 {%0,%1,%2,%3}, [%4];"
    : "=r"(r[0]),"=r"(r[1]),"=r"(r[2]),"=r"(r[3]) : "r"(addr));
}
__device__ __forceinline__ void mma16816(float* d, const uint32_t* a, uint32_t b0, uint32_t b1){
  asm volatile("mma.sync.aligned.m16n8k16.row.col.f32.f16.f16.f32 "
    "{%0,%1,%2,%3}, {%4,%5,%6,%7}, {%8,%9}, {%0,%1,%2,%3};"
    : "+f"(d[0]),"+f"(d[1]),"+f"(d[2]),"+f"(d[3])
    : "r"(a[0]),"r"(a[1]),"r"(a[2]),"r"(a[3]), "r"(b0),"r"(b1));
}
__device__ __forceinline__ void exp2_pair(float a0, float a1, float& w0, float& w1){
  uint32_t hp, ep;
  asm("cvt.rn.f16x2.f32 %0, %1, %2;" : "=r"(hp) : "f"(a1), "f"(a0));
  asm("ex2.approx.f16x2 %0, %1;" : "=r"(ep) : "r"(hp));
  __half2 hh = *(__half2*)&ep;
  w0 = __low2float(hh); w1 = __high2float(hh);
}

#define TILE_B 10240
#define STAGE_B (4*TILE_B)
#define GEMM_SMEM (2*STAGE_B)   // 81920; 2 CTAs/SM

// ---------------- fp16 hi/lo split ----------------
__global__ void k_split(const float* __restrict__ x, __half* __restrict__ hi,
                        __half* __restrict__ lo, int n4){
  int i = blockIdx.x*blockDim.x + threadIdx.x;
  if(i >= n4) return;
  float4 v = ((const float4*)x)[i];
  __half h0=__float2half_rn(v.x), h1=__float2half_rn(v.y);
  __half h2=__float2half_rn(v.z), h3=__float2half_rn(v.w);
  __half l0=__float2half_rn(v.x-__half2float(h0));
  __half l1=__float2half_rn(v.y-__half2float(h1));
  __half l2=__float2half_rn(v.z-__half2float(h2));
  __half l3=__float2half_rn(v.w-__half2float(h3));
  __half2* H=(__half2*)hi;
  __half2* L=(__half2*)lo;
  H[2*i]   = __halves2half2(h0,h1);
  H[2*i+1] = __halves2half2(h2,h3);
  L[2*i]   = __halves2half2(l0,l1);
  L[2*i+1] = __halves2half2(l2,l3);
}

// ---------------- fused epilogue (templated on K) ----------------
template<int KK>
__device__ __forceinline__ void epi_fused(
    char* smem, const float* __restrict__ V, float* __restrict__ Pm,
    float* __restrict__ Ps, float* __restrict__ Po,
    int b, int rt, int ct, int C, int tid, int wid, int lane)
{
  float* sT = (float*)smem;
  const int NT = C >> 7;
  int r0 = rt*128, c0 = ct*128;
  float* Vr = sT + 128*129;
  float* Vc = Vr + 128*KK;
  for(int idx=tid; idx<128*KK; idx+=256){
    Vr[idx] = V[((size_t)b*C + r0)*KK + idx];
    Vc[idx] = V[((size_t)b*C + c0)*KK + idx];
  }
  __syncthreads();
  const float L2E = 1.44269504f;

  // direct band: row band rt, slot ct
  {
    int row = wid*16 + (lane>>1);
    int h = lane&1;
    const float* pr = sT + row*129 + h*64;
    float m = -3.0e38f;
#pragma unroll 8
    for(int j=0;j<64;j++) m = fmaxf(m, -pr[j]);
    m = fmaxf(m, __shfl_xor_sync(0xffffffffu, m, 1));
    float s=0.f, so[KK];
#pragma unroll
    for(int k=0;k<KK;k++) so[k]=0.f;
    const float* vb = Vc + (size_t)(h*64)*KK;
    for(int j=0;j<64;j+=2){
      float w0,w1;
      exp2_pair((-pr[j]-m)*L2E, (-pr[j+1]-m)*L2E, w0,w1);
      s += w0+w1;
      const float* v0 = vb + (size_t)j*KK;
#pragma unroll
      for(int k=0;k<KK;k++) so[k] += w0*v0[k] + w1*v0[KK+k];
    }
    s += __shfl_xor_sync(0xffffffffu, s, 1);
#pragma unroll
    for(int k=0;k<KK;k++) so[k] += __shfl_xor_sync(0xffffffffu, so[k], 1);
    if(!h){
      size_t idx = ((size_t)b*NT + ct)*C + r0 + row;
      Pm[idx]=m; Ps[idx]=s;
#pragma unroll
      for(int k=0;k<KK;k++) Po[idx*KK+k]=so[k];
    }
  }
  // transposed band: row band ct, slot rt (skip diagonal)
  if(rt != ct){
    int col = wid*16 + (lane>>1);
    int h = lane&1;
    const float* pc = sT + col + (size_t)(h*64)*129;
    float m = -3.0e38f;
#pragma unroll 8
    for(int i=0;i<64;i++) m = fmaxf(m, -pc[(size_t)i*129]);
    m = fmaxf(m, __shfl_xor_sync(0xffffffffu, m, 1));
    float s=0.f, so[KK];
#pragma unroll
    for(int k=0;k<KK;k++) so[k]=0.f;
    const float* vb = Vr + (size_t)(h*64)*KK;
    for(int i=0;i<64;i+=2){
      float w0,w1;
      exp2_pair((-pc[(size_t)i*129]-m)*L2E, (-pc[(size_t)(i+1)*129]-m)*L2E, w0,w1);
      s += w0+w1;
      const float* v0 = vb + (size_t)i*KK;
#pragma unroll
      for(int k=0;k<KK;k++) so[k] += w0*v0[k] + w1*v0[KK+k];
    }
    s += __shfl_xor_sync(0xffffffffu, s, 1);
#pragma unroll
    for(int k=0;k<KK;k++) so[k] += __shfl_xor_sync(0xffffffffu, so[k], 1);
    if(!h){
      size_t idx = ((size_t)b*NT + rt)*C + c0 + col;
      Pm[idx]=m; Ps[idx]=s;
#pragma unroll
      for(int k=0;k<KK;k++) Po[idx*KK+k]=so[k];
    }
  }
}

// ---------------- merged HMMA Gram: all 3 levels in one grid (LPT order) ----------------
// tiles [0,10): L2 (C=512,N=4096, E-write); [10,46): L3 (C=1024,N=1024, fused K=9);
// [46,182): L4 (C=2048,N=256, fused K=1)
__global__ __launch_bounds__(256,2)
void k_gram_all(const __half* __restrict__ H4p, const __half* __restrict__ L4p,
                const __half* __restrict__ H3p, const __half* __restrict__ L3p,
                const __half* __restrict__ H2p, const __half* __restrict__ L2p,
                const float* __restrict__ V4, const float* __restrict__ V3,
                float* __restrict__ P4m, float* __restrict__ P4s, float* __restrict__ P4o,
                float* __restrict__ P3m, float* __restrict__ P3s, float* __restrict__ P3o,
                float* __restrict__ E2)
{
  int t = blockIdx.x, b = blockIdx.y;
  const __half *Xhi, *Xlo; int C, N, kf;
  if(t < 10){ Xhi=H2p; Xlo=L2p; C=512;  N=4096; kf=0; }
  else if(t < 46){ t-=10; Xhi=H3p; Xlo=L3p; C=1024; N=1024; kf=9; }
  else { t-=46; Xhi=H4p; Xlo=L4p; C=2048; N=256;  kf=1; }

  int rt = (int)((sqrtf(8.0f*t + 1.0f) - 1.0f) * 0.5f);
  while((rt+1)*(rt+2)/2 <= t) rt++;
  while(rt*(rt+1)/2 > t) rt--;
  int ct = t - rt*(rt+1)/2;

  extern __shared__ char smem[];
  uint32_t sb = s2u(smem);
  int tid = threadIdx.x, wid = tid>>5, lane = tid&31;
  int m0w = (wid>>2)*64;
  int n0w = (wid&3)*32;

  const size_t bCN = (size_t)b*C*N;
  const __half* Ah = Xhi + bCN + (size_t)(rt*128)*N;
  const __half* Al = Xlo + bCN + (size_t)(rt*128)*N;
  const __half* Bh = Xhi + bCN + (size_t)(ct*128)*N;
  const __half* Bl = Xlo + bCN + (size_t)(ct*128)*N;
  const int nch = N >> 5;

  float acc[4][4][4];
#pragma unroll
  for(int i=0;i<4;i++)
#pragma unroll
    for(int j=0;j<4;j++)
#pragma unroll
      for(int q=0;q<4;q++) acc[i][j][q]=0.f;

  #define LOADC(ch, stg) do { \
    uint32_t s0 = sb + (uint32_t)(stg)*STAGE_B; \
    int kbase = (ch)*32; \
    _Pragma("unroll") \
    for(int q=0;q<2;q++){ \
      int id = q*256 + tid; \
      int row = id>>2, cc = id&3; \
      uint32_t d = s0 + (uint32_t)(row*80 + cc*16); \
      size_t go = (size_t)row*N + kbase + cc*8; \
      cp16(d,            Ah + go); \
      cp16(d +   TILE_B, Al + go); \
      cp16(d + 2*TILE_B, Bh + go); \
      cp16(d + 3*TILE_B, Bl + go); \
    } \
  } while(0)

  LOADC(0, 0); cp_commit();

  for(int c=0; c<nch; c++){
    if(c+1 < nch){ LOADC(c+1, (c+1)&1); cp_commit(); cp_wait<1>(); }
    else cp_wait<0>();
    __syncthreads();
    uint32_t sbase = sb + (uint32_t)(c&1)*STAGE_B;
#pragma unroll
    for(int ks=0; ks<2; ks++){
      uint32_t kb = ks*32;
      uint32_t ah[4][4], al[4][4];
#pragma unroll
      for(int i=0;i<4;i++){
        uint32_t ra = sbase + (uint32_t)((m0w + i*16 + (lane&15))*80) + kb + ((lane>>4)<<4);
        ldmx4(ah[i], ra);
        ldmx4(al[i], ra + TILE_B);
      }
      uint32_t bh[2][4], bl[2][4];
#pragma unroll
      for(int p=0;p<2;p++){
        uint32_t rb = sbase + 2*TILE_B + (uint32_t)((n0w + p*16 + (lane&15))*80) + kb + ((lane>>4)<<4);
        ldmx4(bh[p], rb);
        ldmx4(bl[p], rb + TILE_B);
      }
#pragma unroll
      for(int i=0;i<4;i++)
#pragma unroll
        for(int j=0;j<4;j++){
          int p = j>>1, s = j&1;
          mma16816(acc[i][j], ah[i], bh[p][s], bh[p][s+2]);
          mma16816(acc[i][j], ah[i], bl[p][s], bl[p][s+2]);
          mma16816(acc[i][j], al[i], bh[p][s], bh[p][s+2]);
        }
    }
    __syncthreads();
  }
  #undef LOADC

  // ---- stage tile in smem ----
  float* sT = (float*)smem;     // 128 x 129
  int rl = m0w + (lane>>2);
  int cl = n0w + (lane&3)*2;
#pragma unroll
  for(int i=0;i<4;i++)
#pragma unroll
    for(int j=0;j<4;j++){
      int rr = rl + i*16, cc = cl + j*8;
      sT[rr*129 + cc]       = acc[i][j][0];
      sT[rr*129 + cc + 1]   = acc[i][j][1];
      sT[(rr+8)*129 + cc]   = acc[i][j][2];
      sT[(rr+8)*129 + cc+1] = acc[i][j][3];
    }
  __syncthreads();

  int r0 = rt*128, c0 = ct*128;
  if(kf == 0){
    float* Eb = E2 + (size_t)b*C*C;
#pragma unroll 4
    for(int it=0; it<64; it++){
      int idx = it*256 + tid;
      int i = idx>>7, j = idx&127;
      Eb[(size_t)(r0+i)*C + c0 + j] = sT[i*129 + j];
    }
    if(rt != ct){
#pragma unroll 4
      for(int it=0; it<64; it++){
        int idx = it*256 + tid;
        int jj = idx>>7, ii = idx&127;
        Eb[(size_t)(c0+jj)*C + r0 + ii] = sT[ii*129 + jj];
      }
    }
  } else if(kf == 1){
    epi_fused<1>(smem, V4, P4m, P4s, P4o, b, rt, ct, C, tid, wid, lane);
  } else {
    epi_fused<9>(smem, V3, P3m, P3s, P3o, b, rt, ct, C, tid, wid, lane);
  }
}

// ---------------- combine partials -> A[b][C][KF] ----------------
template<int KF>
__global__ void k_comb(const float* __restrict__ Pm, const float* __restrict__ Ps,
                       const float* __restrict__ Po, float* __restrict__ A, int C, int NT){
  int r = blockIdx.x*blockDim.x + threadIdx.x;
  if(r >= NB*C) return;
  int b = r / C; int row = r - b*C;
  float m = -3.0e38f;
  for(int t=0;t<NT;t++) m = fmaxf(m, Pm[((size_t)b*NT+t)*C + row]);
  float s=0.f, so[KF];
#pragma unroll
  for(int k=0;k<KF;k++) so[k]=0.f;
  for(int t=0;t<NT;t++){
    size_t idx = ((size_t)b*NT+t)*C + row;
    float sc = __expf(Pm[idx]-m);
    s += Ps[idx]*sc;
#pragma unroll
    for(int k=0;k<KF;k++) so[k] += Po[idx*KF+k]*sc;
  }
  float inv = 1.f/s;
#pragma unroll
  for(int k=0;k<KF;k++) A[(size_t)r*KF + k] = so[k]*inv;
}

// ---------------- row softmax(-E) @ [V | 1]  (L2, K=49) ----------------
template<int K>
__global__ __launch_bounds__(256) void k_softmax(const float* __restrict__ E,
                                                 const float* __restrict__ V,
                                                 float* __restrict__ A, int C){
  __shared__ float sE[2048];
  __shared__ float sred[8*56];
  __shared__ float sOut[56];
  __shared__ float sm_m;
  int tid = threadIdx.x, wid = tid>>5, lane = tid&31;
  int row = blockIdx.x;
  int b = row / C;
  const float* Er = E + (size_t)row*C;
  float m = -3.0e38f;
  for(int d=tid; d<C; d+=256){ float e = -Er[d]; sE[d]=e; m=fmaxf(m,e); }
#pragma unroll
  for(int o=16;o;o>>=1) m = fmaxf(m, __shfl_xor_sync(0xffffffffu,m,o));
  if(!lane) sred[wid] = m;
  __syncthreads();
  if(tid==0){ float mm=sred[0]; for(int i=1;i<8;i++) mm=fmaxf(mm,sred[i]); sm_m=mm; }
  __syncthreads();
  m = sm_m;
  const float L2E = 1.44269504f;
  float acc[K+1];
#pragma unroll
  for(int k=0;k<=K;k++) acc[k]=0.f;
  const float* Vb = V + (size_t)b*C*K;
  for(int d=tid*2; d<C; d+=512){
    float a0 = (sE[d]-m)*L2E, a1 = (sE[d+1]-m)*L2E;
    float w0, w1; exp2_pair(a0, a1, w0, w1);
    const float* vp0 = Vb + (size_t)d*K;
    const float* vp1 = vp0 + K;
    acc[K] += w0 + w1;
#pragma unroll
    for(int k=0;k<K;k++) acc[k] += w0*vp0[k] + w1*vp1[k];
  }
  __syncthreads();
#pragma unroll
  for(int k=0;k<=K;k++){
    float v = acc[k];
#pragma unroll
    for(int o=16;o;o>>=1) v += __shfl_xor_sync(0xffffffffu,v,o);
    if(!lane) sred[wid*56+k]=v;
  }
  __syncthreads();
  if(tid <= K){
    float t=0.f;
#pragma unroll
    for(int w=0;w<8;w++) t += sred[w*56+tid];
    sOut[tid]=t;
  }
  __syncthreads();
  if(tid < K) A[(size_t)row*K + tid] = sOut[tid]/sOut[K];
}

// ---------------- per-channel spatial sums of c4 ----------------
__global__ void k_sum4(const float* __restrict__ c4){
  int w = (blockIdx.x*blockDim.x + threadIdx.x) >> 5;
  int lane = threadIdx.x & 31;
  if(w >= NB*2048) return;
  const float4* p = (const float4*)(c4 + (size_t)w*256);
  float4 a = p[lane], b = p[lane+32];
  float s = a.x+a.y+a.z+a.w + b.x+b.y+b.z+b.w;
  s = warp_sum(s);
  if(!lane) g_sum4[w] = s;
}

// ---------------- c3 subgrid base sums ----------------
__global__ void k_M3(const float* __restrict__ c3){
  int w = (blockIdx.x*blockDim.x + threadIdx.x) >> 5;
  int lane = threadIdx.x & 31;
  if(w >= NB*1024) return;
  const float4* p = (const float4*)(c3 + (size_t)w*1024 + (size_t)lane*32);
  float ce=0.f, co=0.f, c31=0.f;
  float4 v;
#pragma unroll
  for(int j=0;j<8;j++){ v = p[j]; ce += v.x+v.z; co += v.y+v.w; }
  c31 = v.w;
  bool er = (lane & 1) == 0;
  float Ee = warp_sum(er?ce:0.f), Eo = warp_sum(er?co:0.f), El = warp_sum(er?c31:0.f);
  float Oe = warp_sum(er?0.f:ce), Oo = warp_sum(er?0.f:co), Ol = warp_sum(er?0.f:c31);
  float Le = __shfl_sync(0xffffffffu, ce, 31);
  float Lo = __shfl_sync(0xffffffffu, co, 31);
  float Ll = __shfl_sync(0xffffffffu, c31, 31);
  if(!lane){
    float* o = g_M3 + (size_t)w*9;
    o[0]=Ee; o[1]=Eo; o[2]=El;
    o[3]=Oe; o[4]=Oo; o[5]=Ol;
    o[6]=Le; o[7]=Lo; o[8]=Ll;
  }
}

// ---------------- c2 subgrid base sums ----------------
__global__ void k_M2(const float* __restrict__ c2){
  int w = (blockIdx.x*blockDim.x + threadIdx.x) >> 5;
  int lane = threadIdx.x & 31;
  if(w >= NB*512) return;
  const float* base = c2 + (size_t)w*4096;
  float ra[7], rb[7];
#pragma unroll
  for(int t=0;t<7;t++){ ra[t]=0.f; rb[t]=0.f; }
  {
    const float4* p = (const float4*)(base + (size_t)lane*64);
    float4 v;
#pragma unroll
    for(int j=0;j<16;j++){
      v = p[j];
      ra[0]+=v.x; ra[1]+=v.y; ra[2]+=v.z; ra[3]+=v.w;
    }
    ra[4]=v.y; ra[5]=v.z; ra[6]=v.w;
  }
  {
    const float4* p = (const float4*)(base + (size_t)(lane+32)*64);
    float4 v;
#pragma unroll
    for(int j=0;j<16;j++){
      v = p[j];
      rb[0]+=v.x; rb[1]+=v.y; rb[2]+=v.z; rb[3]+=v.w;
    }
    rb[4]=v.y; rb[5]=v.z; rb[6]=v.w;
  }
  float comb[7];
#pragma unroll
  for(int t=0;t<7;t++) comb[t] = ra[t]+rb[t];
  int m = lane & 3;
  float res[4][7];
#pragma unroll
  for(int rk=0;rk<4;rk++)
#pragma unroll
    for(int t=0;t<7;t++)
      res[rk][t] = warp_sum((m==rk) ? comb[t] : 0.f);
  float sp[3][7];
#pragma unroll
  for(int s=0;s<3;s++)
#pragma unroll
    for(int t=0;t<7;t++)
      sp[s][t] = __shfl_sync(0xffffffffu, rb[t], 29+s);
  if(!lane){
    float* o = g_M2 + (size_t)w*49;
#pragma unroll
    for(int rk=0;rk<4;rk++)
#pragma unroll
      for(int t=0;t<7;t++) o[rk*7+t] = res[rk][t];
#pragma unroll
    for(int s=0;s<3;s++)
#pragma unroll
      for(int t=0;t<7;t++) o[(4+s)*7+t] = sp[s][t];
  }
}

// ---------------- CY ----------------
__global__ void k_CY(const float* __restrict__ g2p){
  int idx = blockIdx.x*blockDim.x + threadIdx.x;
  if(idx >= NB*512) return;
  float g2 = g2p[0];
  const float* Ap = g_A2 + (size_t)idx*49;
  const float* Mp = g_M2 + (size_t)idx*49;
  float Y[49];
#pragma unroll
  for(int t=0;t<49;t++) Y[t] = g2*Ap[t] + Mp[t];
  float T[7][7];
#pragma unroll
  for(int r=0;r<7;r++){
    const float* y = Y + r*7;
    T[r][0]=y[0]; T[r][1]=y[1]; T[r][2]=y[1]-y[4];
    T[r][3]=y[2]; T[r][4]=y[2]-y[5]; T[r][5]=y[3]; T[r][6]=y[3]-y[6];
  }
  float Cc[7][7];
#pragma unroll
  for(int c=0;c<7;c++){
    Cc[0][c]=T[0][c]; Cc[1][c]=T[1][c]; Cc[2][c]=T[1][c]-T[4][c];
    Cc[3][c]=T[2][c]; Cc[4][c]=T[2][c]-T[5][c]; Cc[5][c]=T[3][c]; Cc[6][c]=T[3][c]-T[6][c];
  }
  float* o = g_CY + (size_t)idx*49;
#pragma unroll
  for(int r=0;r<7;r++)
#pragma unroll
    for(int c=0;c<7;c++) o[r*7+c] = Cc[r][c];
}

// ---------------- cam4pool + down4pool ----------------
__global__ void k_cam4(const float* __restrict__ w4, const float* __restrict__ b4,
                       const float* __restrict__ g4p){
  int w = (blockIdx.x*blockDim.x + threadIdx.x) >> 5;
  int lane = threadIdx.x & 31;
  if(w >= NB*512) return;
  int b = w >> 9, o = w & 511;
  float g4 = g4p[0];
  const float* W = w4 + (size_t)o*2048;
  const float* s4 = g_sum4 + (size_t)b*2048;
  const float* a4 = g_A4 + (size_t)b*2048;
  float acc1=0.f, acc2=0.f;
  for(int d=lane; d<2048; d+=32){
    float wv=W[d], sv=s4[d];
    acc1 += wv*sv;
    acc2 += wv*(g4*a4[d]+sv);
  }
  acc1 = warp_sum(acc1); acc2 = warp_sum(acc2);
  if(!lane){
    float dp = acc1*(1.f/256.f) + b4[o];
    g_down4[w] = dp;
    g_cam4[w]  = acc2*(1.f/256.f) + b4[o] + dp;
  }
}

// ---------------- cam3pool ----------------
__global__ void k_cam3(const float* __restrict__ w3, const float* __restrict__ g3p){
  int w = (blockIdx.x*blockDim.x + threadIdx.x) >> 5;
  int lane = threadIdx.x & 31;
  if(w >= NB*512) return;
  int b = w >> 9, o = w & 511;
  float g3 = g3p[0];
  float acc = 0.f;
  for(int i=lane; i<1024; i+=32){
    const float* Ap = g_A3 + ((size_t)b*1024+i)*9;
    const float* Mp = g_M3 + ((size_t)b*1024+i)*9;
    float Y[9];
#pragma unroll
    for(int t=0;t<9;t++) Y[t] = g3*Ap[t] + Mp[t];
    float T[3][3];
#pragma unroll
    for(int rk=0;rk<3;rk++){
      T[rk][0]=Y[rk*3+1]-Y[rk*3+2]; T[rk][1]=Y[rk*3+0]; T[rk][2]=Y[rk*3+1];
    }
    float Cc[3][3];
#pragma unroll
    for(int kw=0;kw<3;kw++){
      Cc[0][kw]=T[1][kw]-T[2][kw]; Cc[1][kw]=T[0][kw]; Cc[2][kw]=T[1][kw];
    }
    const float* wp = w3 + ((size_t)o*1024+i)*9;
#pragma unroll
    for(int kh=0;kh<3;kh++)
#pragma unroll
      for(int kw=0;kw<3;kw++) acc += wp[kh*3+kw]*Cc[kh][kw];
  }
  acc = warp_sum(acc);
  if(!lane) g_cam3[w] = acc*(1.f/256.f) + g_down4[w];
}

// ---------------- SGz ----------------
__global__ void k_SGz(const float* __restrict__ w2a){
  int w = (blockIdx.x*blockDim.x + threadIdx.x) >> 5;
  int lane = threadIdx.x & 31;
  if(w >= NB*512) return;
  int b = w >> 9, c = w & 511;
  float acc[9];
#pragma unroll
  for(int t=0;t<9;t++) acc[t]=0.f;
  const int map0[3] = {2,4,6};
  const int map1[3] = {6,0,1};
  const int map2[3] = {1,3,5};
  for(int i=lane; i<512; i+=32){
    float CY[49];
    const float* cy = g_CY + ((size_t)b*512+i)*49;
#pragma unroll
    for(int t=0;t<49;t++) CY[t]=cy[t];
    float wv[9];
    const float* wp = w2a + ((size_t)c*512+i)*9;
#pragma unroll
    for(int t=0;t<9;t++) wv[t]=wp[t];
#pragma unroll
    for(int kh=0;kh<3;kh++){
      int rA = (kh==0)?0:((kh==1)?1:2);
#pragma unroll
      for(int kw=0;kw<3;kw++){
        float s=0.f;
#pragma unroll
        for(int ka=0;ka<3;ka++){
          int rc = (rA==0)?map0[ka]:((rA==1)?map1[ka]:map2[ka]);
#pragma unroll
          for(int la=0;la<3;la++){
            int cc = (kw==0)?map0[la]:((kw==1)?map1[la]:map2[la]);
            s += wv[ka*3+la]*CY[rc*7+cc];
          }
        }
        acc[kh*3+kw]+=s;
      }
    }
  }
#pragma unroll
  for(int t=0;t<9;t++) acc[t]=warp_sum(acc[t]);
  if(!lane){
    float* o = g_SGz + (size_t)w*9;
#pragma unroll
    for(int t=0;t<9;t++) o[t]=acc[t];
  }
}

// ---------------- cam2pool ----------------
__global__ void k_cam2(const float* __restrict__ w2b, const float* __restrict__ b2b){
  int w = (blockIdx.x*blockDim.x + threadIdx.x) >> 5;
  int lane = threadIdx.x & 31;
  if(w >= NB*512) return;
  int b = w >> 9, o = w & 511;
  float acc=0.f;
  for(int c=lane; c<512; c+=32){
    const float* wp = w2b + ((size_t)o*512+c)*9;
    const float* sg = g_SGz + ((size_t)b*512+c)*9;
#pragma unroll
    for(int t=0;t<9;t++) acc += wp[t]*sg[t];
  }
  acc = warp_sum(acc);
  if(!lane) g_cam2[w] = acc*(1.f/256.f) + b2b[o] + g_down4[w];
}

// ---------------- final FC ----------------
__global__ void k_out(const float* __restrict__ fcw, const float* __restrict__ fcb,
                      float* __restrict__ out){
  int w = (blockIdx.x*blockDim.x + threadIdx.x) >> 5;
  int lane = threadIdx.x & 31;
  if(w >= NB*2) return;
  int b = w >> 1, j = w & 1;
  float acc=0.f;
  for(int idx=lane; idx<3584; idx+=32){
    float f;
    if(idx<512)       f = g_cam2[b*512+idx];
    else if(idx<1024) f = g_cam3[b*512+idx-512];
    else if(idx<1536) f = g_cam4[b*512+idx-1024];
    else              f = g_sum4[b*2048 + idx-1536]*(1.f/256.f);
    acc += f*fcw[(size_t)j*3584+idx];
  }
  acc = warp_sum(acc);
  if(!lane) out[b*2+j] = acc + fcb[j];
}

// ---------------- launch ----------------
extern "C" void kernel_launch(void* const* d_in, const int* in_sizes, int n_in,
                              void* d_out, int out_size){
  const float* c2  = (const float*)d_in[0];
  const float* c3  = (const float*)d_in[1];
  const float* c4  = (const float*)d_in[2];
  const float* w4  = (const float*)d_in[3];
  const float* b4  = (const float*)d_in[4];
  const float* w3  = (const float*)d_in[5];
  const float* w2a = (const float*)d_in[6];
  const float* w2b = (const float*)d_in[7];
  const float* b2b = (const float*)d_in[8];
  const float* g2  = (const float*)d_in[9];
  const float* g3  = (const float*)d_in[10];
  const float* g4  = (const float*)d_in[11];
  const float* fcw = (const float*)d_in[12];
  const float* fcb = (const float*)d_in[13];
  float* out = (float*)d_out;

  void *pS4, *pM3, *pM2, *pA4, *pA3, *pA2;
  void *pH2,*pL2,*pH3,*pL3,*pH4,*pL4,*pE2;
  void *pP4m,*pP4s,*pP4o,*pP3m,*pP3s,*pP3o;
  cudaGetSymbolAddress(&pS4, g_sum4);
  cudaGetSymbolAddress(&pM3, g_M3);
  cudaGetSymbolAddress(&pM2, g_M2);
  cudaGetSymbolAddress(&pA4, g_A4);
  cudaGetSymbolAddress(&pA3, g_A3);
  cudaGetSymbolAddress(&pA2, g_A2);
  cudaGetSymbolAddress(&pH2, g_h2);
  cudaGetSymbolAddress(&pL2, g_l2);
  cudaGetSymbolAddress(&pH3, g_h3);
  cudaGetSymbolAddress(&pL3, g_l3);
  cudaGetSymbolAddress(&pH4, g_h4);
  cudaGetSymbolAddress(&pL4, g_l4);
  cudaGetSymbolAddress(&pE2, g_E2);
  cudaGetSymbolAddress(&pP4m, g_P4m);
  cudaGetSymbolAddress(&pP4s, g_P4s);
  cudaGetSymbolAddress(&pP4o, g_P4o);
  cudaGetSymbolAddress(&pP3m, g_P3m);
  cudaGetSymbolAddress(&pP3s, g_P3s);
  cudaGetSymbolAddress(&pP3o, g_P3o);

  cudaFuncSetAttribute(k_gram_all, cudaFuncAttributeMaxDynamicSharedMemorySize, GEMM_SMEM);

  static cudaStream_t s2 = nullptr, s3 = nullptr;
  static cudaEvent_t evr=nullptr, ev2=nullptr, ev3=nullptr, evG=nullptr, evC2=nullptr, evC3=nullptr;
  if(!s2){
    cudaStreamCreateWithFlags(&s2, cudaStreamNonBlocking);
    cudaStreamCreateWithFlags(&s3, cudaStreamNonBlocking);
    cudaEventCreateWithFlags(&evr, cudaEventDisableTiming);
    cudaEventCreateWithFlags(&ev2, cudaEventDisableTiming);
    cudaEventCreateWithFlags(&ev3, cudaEventDisableTiming);
    cudaEventCreateWithFlags(&evG, cudaEventDisableTiming);
    cudaEventCreateWithFlags(&evC2, cudaEventDisableTiming);
    cudaEventCreateWithFlags(&evC3, cudaEventDisableTiming);
  }

  // fork: pre-phase on 3 streams
  cudaEventRecord(evr, 0);
  cudaStreamWaitEvent(s2, evr, 0);
  cudaStreamWaitEvent(s3, evr, 0);

  // default: c4 prep
  k_split<<<(NB*2048*256/4 + 255)/256, 256>>>(c4, (__half*)pH4, (__half*)pL4, NB*2048*256/4);
  k_sum4<<<NB*2048/8, 256>>>(c4);
  // s2: c3 prep
  k_split<<<(NB*1024*1024/4 + 255)/256, 256, 0, s2>>>(c3, (__half*)pH3, (__half*)pL3, NB*1024*1024/4);
  k_M3<<<NB*1024/8, 256, 0, s2>>>(c3);
  // s3: c2 prep
  k_split<<<(NB*512*4096/4 + 255)/256, 256, 0, s3>>>(c2, (__half*)pH2, (__half*)pL2, NB*512*4096/4);
  k_M2<<<NB*512/8, 256, 0, s3>>>(c2);

  // join pre-phase into default
  cudaEventRecord(ev2, s2);
  cudaEventRecord(ev3, s3);
  cudaStreamWaitEvent(0, ev2, 0);
  cudaStreamWaitEvent(0, ev3, 0);

  // merged gram (LPT order: L2 first, then L3, then L4)
  k_gram_all<<<dim3(182, NB), 256, GEMM_SMEM>>>(
      (__half*)pH4, (__half*)pL4, (__half*)pH3, (__half*)pL3, (__half*)pH2, (__half*)pL2,
      (float*)pS4, (float*)pM3,
      (float*)pP4m, (float*)pP4s, (float*)pP4o,
      (float*)pP3m, (float*)pP3s, (float*)pP3o,
      (float*)pE2);
  cudaEventRecord(evG, 0);
  cudaStreamWaitEvent(s2, evG, 0);
  cudaStreamWaitEvent(s3, evG, 0);

  // post-phase forked
  k_comb<1><<<(NB*2048 + 255)/256, 256>>>((float*)pP4m, (float*)pP4s, (float*)pP4o, (float*)pA4, 2048, 16);
  k_cam4<<<NB*512/8, 256>>>(w4, b4, g4);
  k_comb<9><<<(NB*1024 + 255)/256, 256, 0, s2>>>((float*)pP3m, (float*)pP3s, (float*)pP3o, (float*)pA3, 1024, 8);
  k_softmax<49><<<NB*512, 256, 0, s3>>>((float*)pE2, (float*)pM2, (float*)pA2, 512);
  k_CY<<<(NB*512+255)/256, 256, 0, s3>>>(g2);
  k_SGz<<<NB*512/8, 256, 0, s3>>>(w2a);

  // join for tail
  cudaEventRecord(evC2, s2);
  cudaEventRecord(evC3, s3);
  cudaStreamWaitEvent(0, evC2, 0);
  cudaStreamWaitEvent(0, evC3, 0);

  k_cam3<<<NB*512/8, 256>>>(w3, g3);
  k_cam2<<<NB*512/8, 256>>>(w2b, b2b);
  k_out <<<(NB*2*32+255)/256, 256>>>(fcw, fcb, out);
}

// round 15
// speedup vs baseline: 1.1375x; 1.1375x over previous
#include <cuda_runtime.h>
#include <cuda_fp16.h>
#include <math.h>
#include <stdint.h>

#define NB 16

// ---------------- device scratch ----------------
__device__ float g_sum4[NB*2048];
__device__ float g_M3[NB*1024*9];
__device__ float g_M2[NB*512*49];
__device__ float g_A4[NB*2048];
__device__ float g_A3[NB*1024*9];
__device__ float g_A2[NB*512*49];
__device__ float g_CY[NB*512*49];
__device__ float g_down4[NB*512];
__device__ float g_cam4[NB*512];
__device__ float g_cam3[NB*512];
__device__ float g_cam2[NB*512];
__device__ float g_SGz[NB*512*9];

// fp16 hi/lo splits
__device__ __half g_h2[(size_t)NB*512*4096];
__device__ __half g_l2[(size_t)NB*512*4096];
__device__ __half g_h3[(size_t)NB*1024*1024];
__device__ __half g_l3[(size_t)NB*1024*1024];
__device__ __half g_h4[(size_t)NB*2048*256];
__device__ __half g_l4[(size_t)NB*2048*256];
// Gram scratch: only L2 materializes E
__device__ float g_E2[(size_t)NB*512*512];
// fused-softmax partials: L4 (K=1, NT=16) and L3 (K=9, NT=8)
__device__ float g_P4m[NB*16*2048];
__device__ float g_P4s[NB*16*2048];
__device__ float g_P4o[NB*16*2048];
__device__ float g_P3m[NB*8*1024];
__device__ float g_P3s[NB*8*1024];
__device__ float g_P3o[NB*8*1024*9];

__device__ __forceinline__ float warp_sum(float v){
#pragma unroll
  for(int o=16;o;o>>=1) v += __shfl_xor_sync(0xffffffffu, v, o);
  return v;
}

// ================= PTX helpers =================
__device__ __forceinline__ uint32_t s2u(const void* p){
  uint32_t a; asm("{ .reg .u64 t; cvta.to.shared.u64 t, %1; cvt.u32.u64 %0, t; }":"=r"(a):"l"(p));
  return a;
}
__device__ __forceinline__ void cp16(uint32_t d, const void* s){
  asm volatile("cp.async.cg.shared.global [%0], [%1], 16;\n"
               :: "r"(d), "l"(__cvta_generic_to_global(s)));
}
__device__ __forceinline__ void cp_commit(){ asm volatile("cp.async.commit_group;\n"); }
template<int N> __device__ __forceinline__ void cp_wait(){ asm volatile("cp.async.wait_group %0;\n"::"n"(N)); }

__device__ __forceinline__ void ldmx4(uint32_t* r, uint32_t addr){
  asm volatile("ldmatrix.sync.aligned.m8n8.x4.shared.b16 {%0,%1,%2,%3}, [%4];"
    : "=r"(r[0]),"=r"(r[1]),"=r"(r[2]),"=r"(r[3]) : "r"(addr));
}
__device__ __forceinline__ void mma16816(float* d, const uint32_t* a, uint32_t b0, uint32_t b1){
  asm volatile("mma.sync.aligned.m16n8k16.row.col.f32.f16.f16.f32 "
    "{%0,%1,%2,%3}, {%4,%5,%6,%7}, {%8,%9}, {%0,%1,%2,%3};"
    : "+f"(d[0]),"+f"(d[1]),"+f"(d[2]),"+f"(d[3])
    : "r"(a[0]),"r"(a[1]),"r"(a[2]),"r"(a[3]), "r"(b0),"r"(b1));
}
__device__ __forceinline__ void exp2_pair(float a0, float a1, float& w0, float& w1){
  uint32_t hp, ep;
  asm("cvt.rn.f16x2.f32 %0, %1, %2;" : "=r"(hp) : "f"(a1), "f"(a0));
  asm("ex2.approx.f16x2 %0, %1;" : "=r"(ep) : "r"(hp));
  __half2 hh = *(__half2*)&ep;
  w0 = __low2float(hh); w1 = __high2float(hh);
}

#define TILE_B 10240
#define STAGE_B (4*TILE_B)
#define GEMM_SMEM (2*STAGE_B)   // 81920; 2 CTAs/SM

// ---------------- fp16 hi/lo split ----------------
__global__ void k_split(const float* __restrict__ x, __half* __restrict__ hi,
                        __half* __restrict__ lo, int n4){
  int i = blockIdx.x*blockDim.x + threadIdx.x;
  if(i >= n4) return;
  float4 v = ((const float4*)x)[i];
  __half h0=__float2half_rn(v.x), h1=__float2half_rn(v.y);
  __half h2=__float2half_rn(v.z), h3=__float2half_rn(v.w);
  __half l0=__float2half_rn(v.x-__half2float(h0));
  __half l1=__float2half_rn(v.y-__half2float(h1));
  __half l2=__float2half_rn(v.z-__half2float(h2));
  __half l3=__float2half_rn(v.w-__half2float(h3));
  __half2* H=(__half2*)hi;
  __half2* L=(__half2*)lo;
  H[2*i]   = __halves2half2(h0,h1);
  H[2*i+1] = __halves2half2(h2,h3);
  L[2*i]   = __halves2half2(l0,l1);
  L[2*i+1] = __halves2half2(l2,l3);
}

// ---------------- HMMA Gram (triangular grid) ----------------
// KF=0: materialize E. KF>0: fused per-tile online-softmax partials.
template<int KF>
__global__ __launch_bounds__(256,2)
void k_gram(const __half* __restrict__ Xhi, const __half* __restrict__ Xlo,
            float* __restrict__ E, int C, int N,
            const float* __restrict__ V, float* __restrict__ Pm,
            float* __restrict__ Ps, float* __restrict__ Po)
{
  int t = blockIdx.x;
  int rt = (int)((sqrtf(8.0f*t + 1.0f) - 1.0f) * 0.5f);
  while((rt+1)*(rt+2)/2 <= t) rt++;
  while(rt*(rt+1)/2 > t) rt--;
  int ct = t - rt*(rt+1)/2;
  int b = blockIdx.y;

  extern __shared__ char smem[];
  uint32_t sb = s2u(smem);
  int tid = threadIdx.x, wid = tid>>5, lane = tid&31;
  int m0w = (wid>>2)*64;
  int n0w = (wid&3)*32;

  const size_t bCN = (size_t)b*C*N;
  const __half* Ah = Xhi + bCN + (size_t)(rt*128)*N;
  const __half* Al = Xlo + bCN + (size_t)(rt*128)*N;
  const __half* Bh = Xhi + bCN + (size_t)(ct*128)*N;
  const __half* Bl = Xlo + bCN + (size_t)(ct*128)*N;
  const int nch = N >> 5;

  float acc[4][4][4];
#pragma unroll
  for(int i=0;i<4;i++)
#pragma unroll
    for(int j=0;j<4;j++)
#pragma unroll
      for(int q=0;q<4;q++) acc[i][j][q]=0.f;

  #define LOADC(ch, stg) do { \
    uint32_t s0 = sb + (uint32_t)(stg)*STAGE_B; \
    int kbase = (ch)*32; \
    _Pragma("unroll") \
    for(int q=0;q<2;q++){ \
      int id = q*256 + tid; \
      int row = id>>2, cc = id&3; \
      uint32_t d = s0 + (uint32_t)(row*80 + cc*16); \
      size_t go = (size_t)row*N + kbase + cc*8; \
      cp16(d,            Ah + go); \
      cp16(d +   TILE_B, Al + go); \
      cp16(d + 2*TILE_B, Bh + go); \
      cp16(d + 3*TILE_B, Bl + go); \
    } \
  } while(0)

  LOADC(0, 0); cp_commit();

  for(int c=0; c<nch; c++){
    if(c+1 < nch){ LOADC(c+1, (c+1)&1); cp_commit(); cp_wait<1>(); }
    else cp_wait<0>();
    __syncthreads();
    uint32_t sbase = sb + (uint32_t)(c&1)*STAGE_B;
#pragma unroll
    for(int ks=0; ks<2; ks++){
      uint32_t kb = ks*32;
      uint32_t ah[4][4], al[4][4];
#pragma unroll
      for(int i=0;i<4;i++){
        uint32_t ra = sbase + (uint32_t)((m0w + i*16 + (lane&15))*80) + kb + ((lane>>4)<<4);
        ldmx4(ah[i], ra);
        ldmx4(al[i], ra + TILE_B);
      }
      uint32_t bh[2][4], bl[2][4];
#pragma unroll
      for(int p=0;p<2;p++){
        uint32_t rb = sbase + 2*TILE_B + (uint32_t)((n0w + p*16 + (lane&15))*80) + kb + ((lane>>4)<<4);
        ldmx4(bh[p], rb);
        ldmx4(bl[p], rb + TILE_B);
      }
#pragma unroll
      for(int i=0;i<4;i++)
#pragma unroll
        for(int j=0;j<4;j++){
          int p = j>>1, s = j&1;
          mma16816(acc[i][j], ah[i], bh[p][s], bh[p][s+2]);
          mma16816(acc[i][j], ah[i], bl[p][s], bl[p][s+2]);
          mma16816(acc[i][j], al[i], bh[p][s], bh[p][s+2]);
        }
    }
    __syncthreads();
  }
  #undef LOADC

  // ---- stage tile in smem ----
  float* sT = (float*)smem;     // 128 x 129
  int rl = m0w + (lane>>2);
  int cl = n0w + (lane&3)*2;
#pragma unroll
  for(int i=0;i<4;i++)
#pragma unroll
    for(int j=0;j<4;j++){
      int rr = rl + i*16, cc = cl + j*8;
      sT[rr*129 + cc]       = acc[i][j][0];
      sT[rr*129 + cc + 1]   = acc[i][j][1];
      sT[(rr+8)*129 + cc]   = acc[i][j][2];
      sT[(rr+8)*129 + cc+1] = acc[i][j][3];
    }
  __syncthreads();

  int r0 = rt*128, c0 = ct*128;
  if(KF == 0){
    float* Eb = E + (size_t)b*C*C;
#pragma unroll 4
    for(int it=0; it<64; it++){
      int idx = it*256 + tid;
      int i = idx>>7, j = idx&127;
      Eb[(size_t)(r0+i)*C + c0 + j] = sT[i*129 + j];
    }
    if(rt != ct){
#pragma unroll 4
      for(int it=0; it<64; it++){
        int idx = it*256 + tid;
        int jj = idx>>7, ii = idx&127;
        Eb[(size_t)(c0+jj)*C + r0 + ii] = sT[ii*129 + jj];
      }
    }
    return;
  }

  // ---- fused partial softmax vs V[b][C][KF] ----
  const int NT = C >> 7;
  const int KK = (KF>0)?KF:1;
  float* Vr = sT + 128*129;
  float* Vc = Vr + 128*KK;
  for(int idx=tid; idx<128*KK; idx+=256){
    Vr[idx] = V[((size_t)b*C + r0)*KK + idx];
    Vc[idx] = V[((size_t)b*C + c0)*KK + idx];
  }
  __syncthreads();
  const float L2E = 1.44269504f;

  // direct band: row band rt, slot ct
  {
    int row = wid*16 + (lane>>1);
    int h = lane&1;
    const float* pr = sT + row*129 + h*64;
    float m = -3.0e38f;
#pragma unroll 8
    for(int j=0;j<64;j++) m = fmaxf(m, -pr[j]);
    m = fmaxf(m, __shfl_xor_sync(0xffffffffu, m, 1));
    float s=0.f, so[KK];
#pragma unroll
    for(int k=0;k<KK;k++) so[k]=0.f;
    const float* vb = Vc + (size_t)(h*64)*KK;
    for(int j=0;j<64;j+=2){
      float w0,w1;
      exp2_pair((-pr[j]-m)*L2E, (-pr[j+1]-m)*L2E, w0,w1);
      s += w0+w1;
      const float* v0 = vb + (size_t)j*KK;
#pragma unroll
      for(int k=0;k<KK;k++) so[k] += w0*v0[k] + w1*v0[KK+k];
    }
    s += __shfl_xor_sync(0xffffffffu, s, 1);
#pragma unroll
    for(int k=0;k<KK;k++) so[k] += __shfl_xor_sync(0xffffffffu, so[k], 1);
    if(!h){
      size_t idx = ((size_t)b*NT + ct)*C + r0 + row;
      Pm[idx]=m; Ps[idx]=s;
#pragma unroll
      for(int k=0;k<KK;k++) Po[idx*KK+k]=so[k];
    }
  }
  // transposed band: row band ct, slot rt (skip diagonal)
  if(rt != ct){
    int col = wid*16 + (lane>>1);
    int h = lane&1;
    const float* pc = sT + col + (size_t)(h*64)*129;
    float m = -3.0e38f;
#pragma unroll 8
    for(int i=0;i<64;i++) m = fmaxf(m, -pc[(size_t)i*129]);
    m = fmaxf(m, __shfl_xor_sync(0xffffffffu, m, 1));
    float s=0.f, so[KK];
#pragma unroll
    for(int k=0;k<KK;k++) so[k]=0.f;
    const float* vb = Vr + (size_t)(h*64)*KK;
    for(int i=0;i<64;i+=2){
      float w0,w1;
      exp2_pair((-pc[(size_t)i*129]-m)*L2E, (-pc[(size_t)(i+1)*129]-m)*L2E, w0,w1);
      s += w0+w1;
      const float* v0 = vb + (size_t)i*KK;
#pragma unroll
      for(int k=0;k<KK;k++) so[k] += w0*v0[k] + w1*v0[KK+k];
    }
    s += __shfl_xor_sync(0xffffffffu, s, 1);
#pragma unroll
    for(int k=0;k<KK;k++) so[k] += __shfl_xor_sync(0xffffffffu, so[k], 1);
    if(!h){
      size_t idx = ((size_t)b*NT + rt)*C + c0 + col;
      Pm[idx]=m; Ps[idx]=s;
#pragma unroll
      for(int k=0;k<KK;k++) Po[idx*KK+k]=so[k];
    }
  }
}

// ---------------- combine partials -> A[b][C][KF] ----------------
template<int KF>
__global__ void k_comb(const float* __restrict__ Pm, const float* __restrict__ Ps,
                       const float* __restrict__ Po, float* __restrict__ A, int C, int NT){
  int r = blockIdx.x*blockDim.x + threadIdx.x;
  if(r >= NB*C) return;
  int b = r / C; int row = r - b*C;
  float m = -3.0e38f;
  for(int t=0;t<NT;t++) m = fmaxf(m, Pm[((size_t)b*NT+t)*C + row]);
  float s=0.f, so[KF];
#pragma unroll
  for(int k=0;k<KF;k++) so[k]=0.f;
  for(int t=0;t<NT;t++){
    size_t idx = ((size_t)b*NT+t)*C + row;
    float sc = __expf(Pm[idx]-m);
    s += Ps[idx]*sc;
#pragma unroll
    for(int k=0;k<KF;k++) so[k] += Po[idx*KF+k]*sc;
  }
  float inv = 1.f/s;
#pragma unroll
  for(int k=0;k<KF;k++) A[(size_t)r*KF + k] = so[k]*inv;
}

// ---------------- row softmax(-E) @ [V | 1]  (L2, K=49) ----------------
template<int K>
__global__ __launch_bounds__(256) void k_softmax(const float* __restrict__ E,
                                                 const float* __restrict__ V,
                                                 float* __restrict__ A, int C){
  __shared__ float sE[2048];
  __shared__ float sred[8*56];
  __shared__ float sOut[56];
  __shared__ float sm_m;
  int tid = threadIdx.x, wid = tid>>5, lane = tid&31;
  int row = blockIdx.x;
  int b = row / C;
  const float* Er = E + (size_t)row*C;
  float m = -3.0e38f;
  for(int d=tid; d<C; d+=256){ float e = -Er[d]; sE[d]=e; m=fmaxf(m,e); }
#pragma unroll
  for(int o=16;o;o>>=1) m = fmaxf(m, __shfl_xor_sync(0xffffffffu,m,o));
  if(!lane) sred[wid] = m;
  __syncthreads();
  if(tid==0){ float mm=sred[0]; for(int i=1;i<8;i++) mm=fmaxf(mm,sred[i]); sm_m=mm; }
  __syncthreads();
  m = sm_m;
  const float L2E = 1.44269504f;
  float acc[K+1];
#pragma unroll
  for(int k=0;k<=K;k++) acc[k]=0.f;
  const float* Vb = V + (size_t)b*C*K;
  for(int d=tid*2; d<C; d+=512){
    float a0 = (sE[d]-m)*L2E, a1 = (sE[d+1]-m)*L2E;
    float w0, w1; exp2_pair(a0, a1, w0, w1);
    const float* vp0 = Vb + (size_t)d*K;
    const float* vp1 = vp0 + K;
    acc[K] += w0 + w1;
#pragma unroll
    for(int k=0;k<K;k++) acc[k] += w0*vp0[k] + w1*vp1[k];
  }
  __syncthreads();
#pragma unroll
  for(int k=0;k<=K;k++){
    float v = acc[k];
#pragma unroll
    for(int o=16;o;o>>=1) v += __shfl_xor_sync(0xffffffffu,v,o);
    if(!lane) sred[wid*56+k]=v;
  }
  __syncthreads();
  if(tid <= K){
    float t=0.f;
#pragma unroll
    for(int w=0;w<8;w++) t += sred[w*56+tid];
    sOut[tid]=t;
  }
  __syncthreads();
  if(tid < K) A[(size_t)row*K + tid] = sOut[tid]/sOut[K];
}

// ---------------- per-channel spatial sums of c4 ----------------
__global__ void k_sum4(const float* __restrict__ c4){
  int w = (blockIdx.x*blockDim.x + threadIdx.x) >> 5;
  int lane = threadIdx.x & 31;
  if(w >= NB*2048) return;
  const float4* p = (const float4*)(c4 + (size_t)w*256);
  float4 a = p[lane], b = p[lane+32];
  float s = a.x+a.y+a.z+a.w + b.x+b.y+b.z+b.w;
  s = warp_sum(s);
  if(!lane) g_sum4[w] = s;
}

// ---------------- c3 subgrid base sums ----------------
__global__ void k_M3(const float* __restrict__ c3){
  int w = (blockIdx.x*blockDim.x + threadIdx.x) >> 5;
  int lane = threadIdx.x & 31;
  if(w >= NB*1024) return;
  const float4* p = (const float4*)(c3 + (size_t)w*1024 + (size_t)lane*32);
  float ce=0.f, co=0.f, c31=0.f;
  float4 v;
#pragma unroll
  for(int j=0;j<8;j++){ v = p[j]; ce += v.x+v.z; co += v.y+v.w; }
  c31 = v.w;
  bool er = (lane & 1) == 0;
  float Ee = warp_sum(er?ce:0.f), Eo = warp_sum(er?co:0.f), El = warp_sum(er?c31:0.f);
  float Oe = warp_sum(er?0.f:ce), Oo = warp_sum(er?0.f:co), Ol = warp_sum(er?0.f:c31);
  float Le = __shfl_sync(0xffffffffu, ce, 31);
  float Lo = __shfl_sync(0xffffffffu, co, 31);
  float Ll = __shfl_sync(0xffffffffu, c31, 31);
  if(!lane){
    float* o = g_M3 + (size_t)w*9;
    o[0]=Ee; o[1]=Eo; o[2]=El;
    o[3]=Oe; o[4]=Oo; o[5]=Ol;
    o[6]=Le; o[7]=Lo; o[8]=Ll;
  }
}

// ---------------- c2 subgrid base sums ----------------
__global__ void k_M2(const float* __restrict__ c2){
  int w = (blockIdx.x*blockDim.x + threadIdx.x) >> 5;
  int lane = threadIdx.x & 31;
  if(w >= NB*512) return;
  const float* base = c2 + (size_t)w*4096;
  float ra[7], rb[7];
#pragma unroll
  for(int t=0;t<7;t++){ ra[t]=0.f; rb[t]=0.f; }
  {
    const float4* p = (const float4*)(base + (size_t)lane*64);
    float4 v;
#pragma unroll
    for(int j=0;j<16;j++){
      v = p[j];
      ra[0]+=v.x; ra[1]+=v.y; ra[2]+=v.z; ra[3]+=v.w;
    }
    ra[4]=v.y; ra[5]=v.z; ra[6]=v.w;
  }
  {
    const float4* p = (const float4*)(base + (size_t)(lane+32)*64);
    float4 v;
#pragma unroll
    for(int j=0;j<16;j++){
      v = p[j];
      rb[0]+=v.x; rb[1]+=v.y; rb[2]+=v.z; rb[3]+=v.w;
    }
    rb[4]=v.y; rb[5]=v.z; rb[6]=v.w;
  }
  float comb[7];
#pragma unroll
  for(int t=0;t<7;t++) comb[t] = ra[t]+rb[t];
  int m = lane & 3;
  float res[4][7];
#pragma unroll
  for(int rk=0;rk<4;rk++)
#pragma unroll
    for(int t=0;t<7;t++)
      res[rk][t] = warp_sum((m==rk) ? comb[t] : 0.f);
  float sp[3][7];
#pragma unroll
  for(int s=0;s<3;s++)
#pragma unroll
    for(int t=0;t<7;t++)
      sp[s][t] = __shfl_sync(0xffffffffu, rb[t], 29+s);
  if(!lane){
    float* o = g_M2 + (size_t)w*49;
#pragma unroll
    for(int rk=0;rk<4;rk++)
#pragma unroll
      for(int t=0;t<7;t++) o[rk*7+t] = res[rk][t];
#pragma unroll
    for(int s=0;s<3;s++)
#pragma unroll
      for(int t=0;t<7;t++) o[(4+s)*7+t] = sp[s][t];
  }
}

// ---------------- CY ----------------
__global__ void k_CY(const float* __restrict__ g2p){
  int idx = blockIdx.x*blockDim.x + threadIdx.x;
  if(idx >= NB*512) return;
  float g2 = g2p[0];
  const float* Ap = g_A2 + (size_t)idx*49;
  const float* Mp = g_M2 + (size_t)idx*49;
  float Y[49];
#pragma unroll
  for(int t=0;t<49;t++) Y[t] = g2*Ap[t] + Mp[t];
  float T[7][7];
#pragma unroll
  for(int r=0;r<7;r++){
    const float* y = Y + r*7;
    T[r][0]=y[0]; T[r][1]=y[1]; T[r][2]=y[1]-y[4];
    T[r][3]=y[2]; T[r][4]=y[2]-y[5]; T[r][5]=y[3]; T[r][6]=y[3]-y[6];
  }
  float Cc[7][7];
#pragma unroll
  for(int c=0;c<7;c++){
    Cc[0][c]=T[0][c]; Cc[1][c]=T[1][c]; Cc[2][c]=T[1][c]-T[4][c];
    Cc[3][c]=T[2][c]; Cc[4][c]=T[2][c]-T[5][c]; Cc[5][c]=T[3][c]; Cc[6][c]=T[3][c]-T[6][c];
  }
  float* o = g_CY + (size_t)idx*49;
#pragma unroll
  for(int r=0;r<7;r++)
#pragma unroll
    for(int c=0;c<7;c++) o[r*7+c] = Cc[r][c];
}

// ---------------- cam4pool + down4pool ----------------
__global__ void k_cam4(const float* __restrict__ w4, const float* __restrict__ b4,
                       const float* __restrict__ g4p){
  int w = (blockIdx.x*blockDim.x + threadIdx.x) >> 5;
  int lane = threadIdx.x & 31;
  if(w >= NB*512) return;
  int b = w >> 9, o = w & 511;
  float g4 = g4p[0];
  const float* W = w4 + (size_t)o*2048;
  const float* s4 = g_sum4 + (size_t)b*2048;
  const float* a4 = g_A4 + (size_t)b*2048;
  float acc1=0.f, acc2=0.f;
  for(int d=lane; d<2048; d+=32){
    float wv=W[d], sv=s4[d];
    acc1 += wv*sv;
    acc2 += wv*(g4*a4[d]+sv);
  }
  acc1 = warp_sum(acc1); acc2 = warp_sum(acc2);
  if(!lane){
    float dp = acc1*(1.f/256.f) + b4[o];
    g_down4[w] = dp;
    g_cam4[w]  = acc2*(1.f/256.f) + b4[o] + dp;
  }
}

// ---------------- cam3pool ----------------
__global__ void k_cam3(const float* __restrict__ w3, const float* __restrict__ g3p){
  int w = (blockIdx.x*blockDim.x + threadIdx.x) >> 5;
  int lane = threadIdx.x & 31;
  if(w >= NB*512) return;
  int b = w >> 9, o = w & 511;
  float g3 = g3p[0];
  float acc = 0.f;
  for(int i=lane; i<1024; i+=32){
    const float* Ap = g_A3 + ((size_t)b*1024+i)*9;
    const float* Mp = g_M3 + ((size_t)b*1024+i)*9;
    float Y[9];
#pragma unroll
    for(int t=0;t<9;t++) Y[t] = g3*Ap[t] + Mp[t];
    float T[3][3];
#pragma unroll
    for(int rk=0;rk<3;rk++){
      T[rk][0]=Y[rk*3+1]-Y[rk*3+2]; T[rk][1]=Y[rk*3+0]; T[rk][2]=Y[rk*3+1];
    }
    float Cc[3][3];
#pragma unroll
    for(int kw=0;kw<3;kw++){
      Cc[0][kw]=T[1][kw]-T[2][kw]; Cc[1][kw]=T[0][kw]; Cc[2][kw]=T[1][kw];
    }
    const float* wp = w3 + ((size_t)o*1024+i)*9;
#pragma unroll
    for(int kh=0;kh<3;kh++)
#pragma unroll
      for(int kw=0;kw<3;kw++) acc += wp[kh*3+kw]*Cc[kh][kw];
  }
  acc = warp_sum(acc);
  if(!lane) g_cam3[w] = acc*(1.f/256.f) + g_down4[w];
}

// ---------------- SGz ----------------
__global__ void k_SGz(const float* __restrict__ w2a){
  int w = (blockIdx.x*blockDim.x + threadIdx.x) >> 5;
  int lane = threadIdx.x & 31;
  if(w >= NB*512) return;
  int b = w >> 9, c = w & 511;
  float acc[9];
#pragma unroll
  for(int t=0;t<9;t++) acc[t]=0.f;
  const int map0[3] = {2,4,6};
  const int map1[3] = {6,0,1};
  const int map2[3] = {1,3,5};
  for(int i=lane; i<512; i+=32){
    float CY[49];
    const float* cy = g_CY + ((size_t)b*512+i)*49;
#pragma unroll
    for(int t=0;t<49;t++) CY[t]=cy[t];
    float wv[9];
    const float* wp = w2a + ((size_t)c*512+i)*9;
#pragma unroll
    for(int t=0;t<9;t++) wv[t]=wp[t];
#pragma unroll
    for(int kh=0;kh<3;kh++){
      int rA = (kh==0)?0:((kh==1)?1:2);
#pragma unroll
      for(int kw=0;kw<3;kw++){
        float s=0.f;
#pragma unroll
        for(int ka=0;ka<3;ka++){
          int rc = (rA==0)?map0[ka]:((rA==1)?map1[ka]:map2[ka]);
#pragma unroll
          for(int la=0;la<3;la++){
            int cc = (kw==0)?map0[la]:((kw==1)?map1[la]:map2[la]);
            s += wv[ka*3+la]*CY[rc*7+cc];
          }
        }
        acc[kh*3+kw]+=s;
      }
    }
  }
#pragma unroll
  for(int t=0;t<9;t++) acc[t]=warp_sum(acc[t]);
  if(!lane){
    float* o = g_SGz + (size_t)w*9;
#pragma unroll
    for(int t=0;t<9;t++) o[t]=acc[t];
  }
}

// ---------------- cam2pool ----------------
__global__ void k_cam2(const float* __restrict__ w2b, const float* __restrict__ b2b){
  int w = (blockIdx.x*blockDim.x + threadIdx.x) >> 5;
  int lane = threadIdx.x & 31;
  if(w >= NB*512) return;
  int b = w >> 9, o = w & 511;
  float acc=0.f;
  for(int c=lane; c<512; c+=32){
    const float* wp = w2b + ((size_t)o*512+c)*9;
    const float* sg = g_SGz + ((size_t)b*512+c)*9;
#pragma unroll
    for(int t=0;t<9;t++) acc += wp[t]*sg[t];
  }
  acc = warp_sum(acc);
  if(!lane) g_cam2[w] = acc*(1.f/256.f) + b2b[o] + g_down4[w];
}

// ---------------- final FC ----------------
__global__ void k_out(const float* __restrict__ fcw, const float* __restrict__ fcb,
                      float* __restrict__ out){
  int w = (blockIdx.x*blockDim.x + threadIdx.x) >> 5;
  int lane = threadIdx.x & 31;
  if(w >= NB*2) return;
  int b = w >> 1, j = w & 1;
  float acc=0.f;
  for(int idx=lane; idx<3584; idx+=32){
    float f;
    if(idx<512)       f = g_cam2[b*512+idx];
    else if(idx<1024) f = g_cam3[b*512+idx-512];
    else if(idx<1536) f = g_cam4[b*512+idx-1024];
    else              f = g_sum4[b*2048 + idx-1536]*(1.f/256.f);
    acc += f*fcw[(size_t)j*3584+idx];
  }
  acc = warp_sum(acc);
  if(!lane) out[b*2+j] = acc + fcb[j];
}

// ---------------- launch ----------------
extern "C" void kernel_launch(void* const* d_in, const int* in_sizes, int n_in,
                              void* d_out, int out_size){
  const float* c2  = (const float*)d_in[0];
  const float* c3  = (const float*)d_in[1];
  const float* c4  = (const float*)d_in[2];
  const float* w4  = (const float*)d_in[3];
  const float* b4  = (const float*)d_in[4];
  const float* w3  = (const float*)d_in[5];
  const float* w2a = (const float*)d_in[6];
  const float* w2b = (const float*)d_in[7];
  const float* b2b = (const float*)d_in[8];
  const float* g2  = (const float*)d_in[9];
  const float* g3  = (const float*)d_in[10];
  const float* g4  = (const float*)d_in[11];
  const float* fcw = (const float*)d_in[12];
  const float* fcb = (const float*)d_in[13];
  float* out = (float*)d_out;

  void *pS4, *pM3, *pM2, *pA4, *pA3, *pA2;
  void *pH2,*pL2,*pH3,*pL3,*pH4,*pL4,*pE2;
  void *pP4m,*pP4s,*pP4o,*pP3m,*pP3s,*pP3o;
  cudaGetSymbolAddress(&pS4, g_sum4);
  cudaGetSymbolAddress(&pM3, g_M3);
  cudaGetSymbolAddress(&pM2, g_M2);
  cudaGetSymbolAddress(&pA4, g_A4);
  cudaGetSymbolAddress(&pA3, g_A3);
  cudaGetSymbolAddress(&pA2, g_A2);
  cudaGetSymbolAddress(&pH2, g_h2);
  cudaGetSymbolAddress(&pL2, g_l2);
  cudaGetSymbolAddress(&pH3, g_h3);
  cudaGetSymbolAddress(&pL3, g_l3);
  cudaGetSymbolAddress(&pH4, g_h4);
  cudaGetSymbolAddress(&pL4, g_l4);
  cudaGetSymbolAddress(&pE2, g_E2);
  cudaGetSymbolAddress(&pP4m, g_P4m);
  cudaGetSymbolAddress(&pP4s, g_P4s);
  cudaGetSymbolAddress(&pP4o, g_P4o);
  cudaGetSymbolAddress(&pP3m, g_P3m);
  cudaGetSymbolAddress(&pP3s, g_P3s);
  cudaGetSymbolAddress(&pP3o, g_P3o);

  cudaFuncSetAttribute(k_gram<0>, cudaFuncAttributeMaxDynamicSharedMemorySize, GEMM_SMEM);
  cudaFuncSetAttribute(k_gram<1>, cudaFuncAttributeMaxDynamicSharedMemorySize, GEMM_SMEM);
  cudaFuncSetAttribute(k_gram<9>, cudaFuncAttributeMaxDynamicSharedMemorySize, GEMM_SMEM);

  static cudaStream_t s2 = nullptr, s3 = nullptr;
  static cudaEvent_t evr = nullptr, ev2 = nullptr, ev3 = nullptr;
  if(!s2){
    cudaStreamCreateWithFlags(&s2, cudaStreamNonBlocking);
    cudaStreamCreateWithFlags(&s3, cudaStreamNonBlocking);
    cudaEventCreateWithFlags(&evr, cudaEventDisableTiming);
    cudaEventCreateWithFlags(&ev2, cudaEventDisableTiming);
    cudaEventCreateWithFlags(&ev3, cudaEventDisableTiming);
  }

  // fork
  cudaEventRecord(evr, 0);
  cudaStreamWaitEvent(s2, evr, 0);
  cudaStreamWaitEvent(s3, evr, 0);

  // ---- chain L2 on s3 (longest critical path: enqueue first) ----
  k_split<<<(NB*512*4096/4 + 255)/256, 256, 0, s3>>>(c2, (__half*)pH2, (__half*)pL2, NB*512*4096/4);
  k_gram<0><<<dim3(4*5/2, NB), 256, GEMM_SMEM, s3>>>((__half*)pH2, (__half*)pL2, (float*)pE2, 512, 4096,
      nullptr, nullptr, nullptr, nullptr);
  k_M2<<<NB*512/8, 256, 0, s3>>>(c2);
  k_softmax<49><<<NB*512, 256, 0, s3>>>((float*)pE2, (float*)pM2, (float*)pA2, 512);

  // ---- chain L3 on s2 (fused K=9) ----
  k_M3<<<NB*1024/8, 256, 0, s2>>>(c3);
  k_split<<<(NB*1024*1024/4 + 255)/256, 256, 0, s2>>>(c3, (__half*)pH3, (__half*)pL3, NB*1024*1024/4);
  k_gram<9><<<dim3(8*9/2, NB), 256, GEMM_SMEM, s2>>>((__half*)pH3, (__half*)pL3, nullptr, 1024, 1024,
      (float*)pM3, (float*)pP3m, (float*)pP3s, (float*)pP3o);
  k_comb<9><<<(NB*1024 + 255)/256, 256, 0, s2>>>((float*)pP3m, (float*)pP3s, (float*)pP3o, (float*)pA3, 1024, 8);

  // ---- chain L4 on default stream (fused K=1) ----
  k_sum4<<<NB*2048/8, 256>>>(c4);
  k_split<<<(NB*2048*256/4 + 255)/256, 256>>>(c4, (__half*)pH4, (__half*)pL4, NB*2048*256/4);
  k_gram<1><<<dim3(16*17/2, NB), 256, GEMM_SMEM>>>((__half*)pH4, (__half*)pL4, nullptr, 2048, 256,
      (float*)pS4, (float*)pP4m, (float*)pP4s, (float*)pP4o);
  k_comb<1><<<(NB*2048 + 255)/256, 256>>>((float*)pP4m, (float*)pP4s, (float*)pP4o, (float*)pA4, 2048, 16);

  // join
  cudaEventRecord(ev2, s2);
  cudaEventRecord(ev3, s3);
  cudaStreamWaitEvent(0, ev2, 0);
  cudaStreamWaitEvent(0, ev3, 0);

  // ---- tail ----
  k_CY  <<<(NB*512+255)/256, 256>>>(g2);
  k_cam4<<<NB*512/8, 256>>>(w4, b4, g4);
  k_cam3<<<NB*512/8, 256>>>(w3, g3);
  k_SGz <<<NB*512/8, 256>>>(w2a);
  k_cam2<<<NB*512/8, 256>>>(w2b, b2b);
  k_out <<<(NB*2*32+255)/256, 256>>>(fcw, fcb, out);
}

// round 17
// speedup vs baseline: 1.3496x; 1.1865x over previous
#include <cuda_runtime.h>
#include <cuda_fp16.h>
#include <math.h>
#include <stdint.h>

#define NB 16

// ---------------- device scratch ----------------
__device__ float g_sum4[NB*2048];
__device__ float g_M3[NB*1024*9];
__device__ float g_M2[NB*512*49];
__device__ float g_A4[NB*2048];
__device__ float g_A3[NB*1024*9];
__device__ float g_A2[NB*512*49];
__device__ float g_CY[NB*512*49];
__device__ float g_down4[NB*512];
__device__ float g_cam4[NB*512];
__device__ float g_cam3[NB*512];
__device__ float g_cam2[NB*512];
__device__ float g_SGz[NB*512*9];

// fp16 hi/lo splits
__device__ __half g_h2[(size_t)NB*512*4096];
__device__ __half g_l2[(size_t)NB*512*4096];
__device__ __half g_h3[(size_t)NB*1024*1024];
__device__ __half g_l3[(size_t)NB*1024*1024];
__device__ __half g_h4[(size_t)NB*2048*256];
__device__ __half g_l4[(size_t)NB*2048*256];
// Gram scratch: only L2 materializes E
__device__ float g_E2[(size_t)NB*512*512];
// fused-softmax partials: L4 (K=1, NT=16) and L3 (K=9, NT=8)
__device__ float g_P4m[NB*16*2048];
__device__ float g_P4s[NB*16*2048];
__device__ float g_P4o[NB*16*2048];
__device__ float g_P3m[NB*8*1024];
__device__ float g_P3s[NB*8*1024];
__device__ float g_P3o[NB*8*1024*9];

__device__ __forceinline__ float warp_sum(float v){
#pragma unroll
  for(int o=16;o;o>>=1) v += __shfl_xor_sync(0xffffffffu, v, o);
  return v;
}

// ================= PTX helpers =================
__device__ __forceinline__ uint32_t s2u(const void* p){
  uint32_t a; asm("{ .reg .u64 t; cvta.to.shared.u64 t, %1; cvt.u32.u64 %0, t; }":"=r"(a):"l"(p));
  return a;
}
__device__ __forceinline__ void cp16(uint32_t d, const void* s){
  asm volatile("cp.async.cg.shared.global [%0], [%1], 16;\n"
               :: "r"(d), "l"(__cvta_generic_to_global(s)));
}
__device__ __forceinline__ void cp_commit(){ asm volatile("cp.async.commit_group;\n"); }
template<int N> __device__ __forceinline__ void cp_wait(){ asm volatile("cp.async.wait_group %0;\n"::"n"(N)); }

__device__ __forceinline__ void ldmx4(uint32_t* r, uint32_t addr){
  asm volatile("ldmatrix.sync.aligned.m8n8.x4.shared.b16 {%0,%1,%2,%3}, [%4];"
    : "=r"(r[0]),"=r"(r[1]),"=r"(r[2]),"=r"(r[3]) : "r"(addr));
}
__device__ __forceinline__ void mma16816(float* d, const uint32_t* a, uint32_t b0, uint32_t b1){
  asm volatile("mma.sync.aligned.m16n8k16.row.col.f32.f16.f16.f32 "
    "{%0,%1,%2,%3}, {%4,%5,%6,%7}, {%8,%9}, {%0,%1,%2,%3};"
    : "+f"(d[0]),"+f"(d[1]),"+f"(d[2]),"+f"(d[3])
    : "r"(a[0]),"r"(a[1]),"r"(a[2]),"r"(a[3]), "r"(b0),"r"(b1));
}
__device__ __forceinline__ void exp2_pair(float a0, float a1, float& w0, float& w1){
  uint32_t hp, ep;
  asm("cvt.rn.f16x2.f32 %0, %1, %2;" : "=r"(hp) : "f"(a1), "f"(a0));
  asm("ex2.approx.f16x2 %0, %1;" : "=r"(ep) : "r"(hp));
  __half2 hh = *(__half2*)&ep;
  w0 = __low2float(hh); w1 = __high2float(hh);
}

#define TILE_B 10240
#define STAGE_B (4*TILE_B)
#define GEMM_SMEM (2*STAGE_B)   // 81920; 2 CTAs/SM

// ---------------- fp16 hi/lo split ----------------
__global__ void k_split(const float* __restrict__ x, __half* __restrict__ hi,
                        __half* __restrict__ lo, int n4){
  int i = blockIdx.x*blockDim.x + threadIdx.x;
  if(i >= n4) return;
  float4 v = ((const float4*)x)[i];
  __half h0=__float2half_rn(v.x), h1=__float2half_rn(v.y);
  __half h2=__float2half_rn(v.z), h3=__float2half_rn(v.w);
  __half l0=__float2half_rn(v.x-__half2float(h0));
  __half l1=__float2half_rn(v.y-__half2float(h1));
  __half l2=__float2half_rn(v.z-__half2float(h2));
  __half l3=__float2half_rn(v.w-__half2float(h3));
  __half2* H=(__half2*)hi;
  __half2* L=(__half2*)lo;
  H[2*i]   = __halves2half2(h0,h1);
  H[2*i+1] = __halves2half2(h2,h3);
  L[2*i]   = __halves2half2(l0,l1);
  L[2*i+1] = __halves2half2(l2,l3);
}

// ---------------- HMMA Gram (triangular grid) ----------------
// KF=0: materialize E. KF>0: fused per-tile online-softmax partials.
template<int KF>
__global__ __launch_bounds__(256,2)
void k_gram(const __half* __restrict__ Xhi, const __half* __restrict__ Xlo,
            float* __restrict__ E, int C, int N,
            const float* __restrict__ V, float* __restrict__ Pm,
            float* __restrict__ Ps, float* __restrict__ Po)
{
  int t = blockIdx.x;
  int rt = (int)((sqrtf(8.0f*t + 1.0f) - 1.0f) * 0.5f);
  while((rt+1)*(rt+2)/2 <= t) rt++;
  while(rt*(rt+1)/2 > t) rt--;
  int ct = t - rt*(rt+1)/2;
  int b = blockIdx.y;

  extern __shared__ char smem[];
  uint32_t sb = s2u(smem);
  int tid = threadIdx.x, wid = tid>>5, lane = tid&31;
  int m0w = (wid>>2)*64;
  int n0w = (wid&3)*32;

  const size_t bCN = (size_t)b*C*N;
  const __half* Ah = Xhi + bCN + (size_t)(rt*128)*N;
  const __half* Al = Xlo + bCN + (size_t)(rt*128)*N;
  const __half* Bh = Xhi + bCN + (size_t)(ct*128)*N;
  const __half* Bl = Xlo + bCN + (size_t)(ct*128)*N;
  const int nch = N >> 5;

  float acc[4][4][4];
#pragma unroll
  for(int i=0;i<4;i++)
#pragma unroll
    for(int j=0;j<4;j++)
#pragma unroll
      for(int q=0;q<4;q++) acc[i][j][q]=0.f;

  #define LOADC(ch, stg) do { \
    uint32_t s0 = sb + (uint32_t)(stg)*STAGE_B; \
    int kbase = (ch)*32; \
    _Pragma("unroll") \
    for(int q=0;q<2;q++){ \
      int id = q*256 + tid; \
      int row = id>>2, cc = id&3; \
      uint32_t d = s0 + (uint32_t)(row*80 + cc*16); \
      size_t go = (size_t)row*N + kbase + cc*8; \
      cp16(d,            Ah + go); \
      cp16(d +   TILE_B, Al + go); \
      cp16(d + 2*TILE_B, Bh + go); \
      cp16(d + 3*TILE_B, Bl + go); \
    } \
  } while(0)

  LOADC(0, 0); cp_commit();

  for(int c=0; c<nch; c++){
    if(c+1 < nch){ LOADC(c+1, (c+1)&1); cp_commit(); cp_wait<1>(); }
    else cp_wait<0>();
    __syncthreads();
    uint32_t sbase = sb + (uint32_t)(c&1)*STAGE_B;
#pragma unroll
    for(int ks=0; ks<2; ks++){
      uint32_t kb = ks*32;
      uint32_t ah[4][4], al[4][4];
#pragma unroll
      for(int i=0;i<4;i++){
        uint32_t ra = sbase + (uint32_t)((m0w + i*16 + (lane&15))*80) + kb + ((lane>>4)<<4);
        ldmx4(ah[i], ra);
        ldmx4(al[i], ra + TILE_B);
      }
      uint32_t bh[2][4], bl[2][4];
#pragma unroll
      for(int p=0;p<2;p++){
        uint32_t rb = sbase + 2*TILE_B + (uint32_t)((n0w + p*16 + (lane&15))*80) + kb + ((lane>>4)<<4);
        ldmx4(bh[p], rb);
        ldmx4(bl[p], rb + TILE_B);
      }
#pragma unroll
      for(int i=0;i<4;i++)
#pragma unroll
        for(int j=0;j<4;j++){
          int p = j>>1, s = j&1;
          mma16816(acc[i][j], ah[i], bh[p][s], bh[p][s+2]);
          mma16816(acc[i][j], ah[i], bl[p][s], bl[p][s+2]);
          mma16816(acc[i][j], al[i], bh[p][s], bh[p][s+2]);
        }
    }
    __syncthreads();
  }
  #undef LOADC

  // ---- stage tile in smem ----
  float* sT = (float*)smem;     // 128 x 129
  int rl = m0w + (lane>>2);
  int cl = n0w + (lane&3)*2;
#pragma unroll
  for(int i=0;i<4;i++)
#pragma unroll
    for(int j=0;j<4;j++){
      int rr = rl + i*16, cc = cl + j*8;
      sT[rr*129 + cc]       = acc[i][j][0];
      sT[rr*129 + cc + 1]   = acc[i][j][1];
      sT[(rr+8)*129 + cc]   = acc[i][j][2];
      sT[(rr+8)*129 + cc+1] = acc[i][j][3];
    }
  __syncthreads();

  int r0 = rt*128, c0 = ct*128;
  if(KF == 0){
    float* Eb = E + (size_t)b*C*C;
#pragma unroll 4
    for(int it=0; it<64; it++){
      int idx = it*256 + tid;
      int i = idx>>7, j = idx&127;
      Eb[(size_t)(r0+i)*C + c0 + j] = sT[i*129 + j];
    }
    if(rt != ct){
#pragma unroll 4
      for(int it=0; it<64; it++){
        int idx = it*256 + tid;
        int jj = idx>>7, ii = idx&127;
        Eb[(size_t)(c0+jj)*C + r0 + ii] = sT[ii*129 + jj];
      }
    }
    return;
  }

  // ---- fused partial softmax vs V[b][C][KF] ----
  const int NT = C >> 7;
  const int KK = (KF>0)?KF:1;
  float* Vr = sT + 128*129;
  float* Vc = Vr + 128*KK;
  for(int idx=tid; idx<128*KK; idx+=256){
    Vr[idx] = V[((size_t)b*C + r0)*KK + idx];
    Vc[idx] = V[((size_t)b*C + c0)*KK + idx];
  }
  __syncthreads();
  const float L2E = 1.44269504f;

  // direct band: row band rt, slot ct
  {
    int row = wid*16 + (lane>>1);
    int h = lane&1;
    const float* pr = sT + row*129 + h*64;
    float m = -3.0e38f;
#pragma unroll 8
    for(int j=0;j<64;j++) m = fmaxf(m, -pr[j]);
    m = fmaxf(m, __shfl_xor_sync(0xffffffffu, m, 1));
    float s=0.f, so[KK];
#pragma unroll
    for(int k=0;k<KK;k++) so[k]=0.f;
    const float* vb = Vc + (size_t)(h*64)*KK;
    for(int j=0;j<64;j+=2){
      float w0,w1;
      exp2_pair((-pr[j]-m)*L2E, (-pr[j+1]-m)*L2E, w0,w1);
      s += w0+w1;
      const float* v0 = vb + (size_t)j*KK;
#pragma unroll
      for(int k=0;k<KK;k++) so[k] += w0*v0[k] + w1*v0[KK+k];
    }
    s += __shfl_xor_sync(0xffffffffu, s, 1);
#pragma unroll
    for(int k=0;k<KK;k++) so[k] += __shfl_xor_sync(0xffffffffu, so[k], 1);
    if(!h){
      size_t idx = ((size_t)b*NT + ct)*C + r0 + row;
      Pm[idx]=m; Ps[idx]=s;
#pragma unroll
      for(int k=0;k<KK;k++) Po[idx*KK+k]=so[k];
    }
  }
  // transposed band: row band ct, slot rt (skip diagonal)
  if(rt != ct){
    int col = wid*16 + (lane>>1);
    int h = lane&1;
    const float* pc = sT + col + (size_t)(h*64)*129;
    float m = -3.0e38f;
#pragma unroll 8
    for(int i=0;i<64;i++) m = fmaxf(m, -pc[(size_t)i*129]);
    m = fmaxf(m, __shfl_xor_sync(0xffffffffu, m, 1));
    float s=0.f, so[KK];
#pragma unroll
    for(int k=0;k<KK;k++) so[k]=0.f;
    const float* vb = Vr + (size_t)(h*64)*KK;
    for(int i=0;i<64;i+=2){
      float w0,w1;
      exp2_pair((-pc[(size_t)i*129]-m)*L2E, (-pc[(size_t)(i+1)*129]-m)*L2E, w0,w1);
      s += w0+w1;
      const float* v0 = vb + (size_t)i*KK;
#pragma unroll
      for(int k=0;k<KK;k++) so[k] += w0*v0[k] + w1*v0[KK+k];
    }
    s += __shfl_xor_sync(0xffffffffu, s, 1);
#pragma unroll
    for(int k=0;k<KK;k++) so[k] += __shfl_xor_sync(0xffffffffu, so[k], 1);
    if(!h){
      size_t idx = ((size_t)b*NT + rt)*C + c0 + col;
      Pm[idx]=m; Ps[idx]=s;
#pragma unroll
      for(int k=0;k<KK;k++) Po[idx*KK+k]=so[k];
    }
  }
}

// ---------------- combine partials -> A[b][C][KF] ----------------
template<int KF>
__global__ void k_comb(const float* __restrict__ Pm, const float* __restrict__ Ps,
                       const float* __restrict__ Po, float* __restrict__ A, int C, int NT){
  int r = blockIdx.x*blockDim.x + threadIdx.x;
  if(r >= NB*C) return;
  int b = r / C; int row = r - b*C;
  float m = -3.0e38f;
  for(int t=0;t<NT;t++) m = fmaxf(m, Pm[((size_t)b*NT+t)*C + row]);
  float s=0.f, so[KF];
#pragma unroll
  for(int k=0;k<KF;k++) so[k]=0.f;
  for(int t=0;t<NT;t++){
    size_t idx = ((size_t)b*NT+t)*C + row;
    float sc = __expf(Pm[idx]-m);
    s += Ps[idx]*sc;
#pragma unroll
    for(int k=0;k<KF;k++) so[k] += Po[idx*KF+k]*sc;
  }
  float inv = 1.f/s;
#pragma unroll
  for(int k=0;k<KF;k++) A[(size_t)r*KF + k] = so[k]*inv;
}

// ---------------- L2 softmax·V: warp-per-row, V staged in smem ----------------
// grid.x = NB*512/8; 8 warps = 8 rows. Dynamic smem: 512*49 floats (V[b]).
__global__ __launch_bounds__(256) void k_sm49(const float* __restrict__ E,
                                              const float* __restrict__ V,
                                              float* __restrict__ A){
  const int C = 512, K = 49;
  extern __shared__ float sV[];            // C*K = 25088 floats
  int tid = threadIdx.x, wid = tid>>5, lane = tid&31;
  int b  = blockIdx.x >> 6;                // 64 row-groups per batch
  int rg = blockIdx.x & 63;
  int row = rg*8 + wid;

  const float* Vb = V + (size_t)b*C*K;
  for(int i=tid; i<C*K; i+=256) sV[i] = Vb[i];
  __syncthreads();

  const float* Er = E + ((size_t)b*C + row)*C;
  float e[16];
  float m = -3.0e38f;
#pragma unroll
  for(int i=0;i<16;i++){ e[i] = -Er[lane + 32*i]; m = fmaxf(m, e[i]); }
#pragma unroll
  for(int o=16;o;o>>=1) m = fmaxf(m, __shfl_xor_sync(0xffffffffu, m, o));

  const float L2E = 1.44269504f;
  float acc[K+1];
#pragma unroll
  for(int k=0;k<=K;k++) acc[k]=0.f;
#pragma unroll
  for(int i=0;i<16;i+=2){
    float w0, w1;
    exp2_pair((e[i]-m)*L2E, (e[i+1]-m)*L2E, w0, w1);
    acc[K] += w0 + w1;
    const float* v0 = sV + (size_t)(lane + 32*i)*K;
    const float* v1 = sV + (size_t)(lane + 32*(i+1))*K;
#pragma unroll
    for(int k=0;k<K;k++) acc[k] += w0*v0[k] + w1*v1[k];
  }
#pragma unroll
  for(int k=0;k<=K;k++){
#pragma unroll
    for(int o=16;o;o>>=1) acc[k] += __shfl_xor_sync(0xffffffffu, acc[k], o);
  }
  if(!lane){
    float inv = 1.f/acc[K];
    float* Ar = A + ((size_t)b*C + row)*K;
#pragma unroll
    for(int k=0;k<K;k++) Ar[k] = acc[k]*inv;
  }
}

// ---------------- per-channel spatial sums of c4 ----------------
__global__ void k_sum4(const float* __restrict__ c4){
  int w = (blockIdx.x*blockDim.x + threadIdx.x) >> 5;
  int lane = threadIdx.x & 31;
  if(w >= NB*2048) return;
  const float4* p = (const float4*)(c4 + (size_t)w*256);
  float4 a = p[lane], b = p[lane+32];
  float s = a.x+a.y+a.z+a.w + b.x+b.y+b.z+b.w;
  s = warp_sum(s);
  if(!lane) g_sum4[w] = s;
}

// ---------------- c3 subgrid base sums ----------------
__global__ void k_M3(const float* __restrict__ c3){
  int w = (blockIdx.x*blockDim.x + threadIdx.x) >> 5;
  int lane = threadIdx.x & 31;
  if(w >= NB*1024) return;
  const float4* p = (const float4*)(c3 + (size_t)w*1024 + (size_t)lane*32);
  float ce=0.f, co=0.f, c31=0.f;
  float4 v;
#pragma unroll
  for(int j=0;j<8;j++){ v = p[j]; ce += v.x+v.z; co += v.y+v.w; }
  c31 = v.w;
  bool er = (lane & 1) == 0;
  float Ee = warp_sum(er?ce:0.f), Eo = warp_sum(er?co:0.f), El = warp_sum(er?c31:0.f);
  float Oe = warp_sum(er?0.f:ce), Oo = warp_sum(er?0.f:co), Ol = warp_sum(er?0.f:c31);
  float Le = __shfl_sync(0xffffffffu, ce, 31);
  float Lo = __shfl_sync(0xffffffffu, co, 31);
  float Ll = __shfl_sync(0xffffffffu, c31, 31);
  if(!lane){
    float* o = g_M3 + (size_t)w*9;
    o[0]=Ee; o[1]=Eo; o[2]=El;
    o[3]=Oe; o[4]=Oo; o[5]=Ol;
    o[6]=Le; o[7]=Lo; o[8]=Ll;
  }
}

// ---------------- c2 subgrid base sums ----------------
__global__ void k_M2(const float* __restrict__ c2){
  int w = (blockIdx.x*blockDim.x + threadIdx.x) >> 5;
  int lane = threadIdx.x & 31;
  if(w >= NB*512) return;
  const float* base = c2 + (size_t)w*4096;
  float ra[7], rb[7];
#pragma unroll
  for(int t=0;t<7;t++){ ra[t]=0.f; rb[t]=0.f; }
  {
    const float4* p = (const float4*)(base + (size_t)lane*64);
    float4 v;
#pragma unroll
    for(int j=0;j<16;j++){
      v = p[j];
      ra[0]+=v.x; ra[1]+=v.y; ra[2]+=v.z; ra[3]+=v.w;
    }
    ra[4]=v.y; ra[5]=v.z; ra[6]=v.w;
  }
  {
    const float4* p = (const float4*)(base + (size_t)(lane+32)*64);
    float4 v;
#pragma unroll
    for(int j=0;j<16;j++){
      v = p[j];
      rb[0]+=v.x; rb[1]+=v.y; rb[2]+=v.z; rb[3]+=v.w;
    }
    rb[4]=v.y; rb[5]=v.z; rb[6]=v.w;
  }
  float comb[7];
#pragma unroll
  for(int t=0;t<7;t++) comb[t] = ra[t]+rb[t];
  int m = lane & 3;
  float res[4][7];
#pragma unroll
  for(int rk=0;rk<4;rk++)
#pragma unroll
    for(int t=0;t<7;t++)
      res[rk][t] = warp_sum((m==rk) ? comb[t] : 0.f);
  float sp[3][7];
#pragma unroll
  for(int s=0;s<3;s++)
#pragma unroll
    for(int t=0;t<7;t++)
      sp[s][t] = __shfl_sync(0xffffffffu, rb[t], 29+s);
  if(!lane){
    float* o = g_M2 + (size_t)w*49;
#pragma unroll
    for(int rk=0;rk<4;rk++)
#pragma unroll
      for(int t=0;t<7;t++) o[rk*7+t] = res[rk][t];
#pragma unroll
    for(int s=0;s<3;s++)
#pragma unroll
      for(int t=0;t<7;t++) o[(4+s)*7+t] = sp[s][t];
  }
}

// ---------------- CY ----------------
__global__ void k_CY(const float* __restrict__ g2p){
  int idx = blockIdx.x*blockDim.x + threadIdx.x;
  if(idx >= NB*512) return;
  float g2 = g2p[0];
  const float* Ap = g_A2 + (size_t)idx*49;
  const float* Mp = g_M2 + (size_t)idx*49;
  float Y[49];
#pragma unroll
  for(int t=0;t<49;t++) Y[t] = g2*Ap[t] + Mp[t];
  float T[7][7];
#pragma unroll
  for(int r=0;r<7;r++){
    const float* y = Y + r*7;
    T[r][0]=y[0]; T[r][1]=y[1]; T[r][2]=y[1]-y[4];
    T[r][3]=y[2]; T[r][4]=y[2]-y[5]; T[r][5]=y[3]; T[r][6]=y[3]-y[6];
  }
  float Cc[7][7];
#pragma unroll
  for(int c=0;c<7;c++){
    Cc[0][c]=T[0][c]; Cc[1][c]=T[1][c]; Cc[2][c]=T[1][c]-T[4][c];
    Cc[3][c]=T[2][c]; Cc[4][c]=T[2][c]-T[5][c]; Cc[5][c]=T[3][c]; Cc[6][c]=T[3][c]-T[6][c];
  }
  float* o = g_CY + (size_t)idx*49;
#pragma unroll
  for(int r=0;r<7;r++)
#pragma unroll
    for(int c=0;c<7;c++) o[r*7+c] = Cc[r][c];
}

// ---------------- cam4pool + down4pool ----------------
__global__ void k_cam4(const float* __restrict__ w4, const float* __restrict__ b4,
                       const float* __restrict__ g4p){
  int w = (blockIdx.x*blockDim.x + threadIdx.x) >> 5;
  int lane = threadIdx.x & 31;
  if(w >= NB*512) return;
  int b = w >> 9, o = w & 511;
  float g4 = g4p[0];
  const float* W = w4 + (size_t)o*2048;
  const float* s4 = g_sum4 + (size_t)b*2048;
  const float* a4 = g_A4 + (size_t)b*2048;
  float acc1=0.f, acc2=0.f;
  for(int d=lane; d<2048; d+=32){
    float wv=W[d], sv=s4[d];
    acc1 += wv*sv;
    acc2 += wv*(g4*a4[d]+sv);
  }
  acc1 = warp_sum(acc1); acc2 = warp_sum(acc2);
  if(!lane){
    float dp = acc1*(1.f/256.f) + b4[o];
    g_down4[w] = dp;
    g_cam4[w]  = acc2*(1.f/256.f) + b4[o] + dp;
  }
}

// ---------------- cam3pool ----------------
__global__ void k_cam3(const float* __restrict__ w3, const float* __restrict__ g3p){
  int w = (blockIdx.x*blockDim.x + threadIdx.x) >> 5;
  int lane = threadIdx.x & 31;
  if(w >= NB*512) return;
  int b = w >> 9, o = w & 511;
  float g3 = g3p[0];
  float acc = 0.f;
  for(int i=lane; i<1024; i+=32){
    const float* Ap = g_A3 + ((size_t)b*1024+i)*9;
    const float* Mp = g_M3 + ((size_t)b*1024+i)*9;
    float Y[9];
#pragma unroll
    for(int t=0;t<9;t++) Y[t] = g3*Ap[t] + Mp[t];
    float T[3][3];
#pragma unroll
    for(int rk=0;rk<3;rk++){
      T[rk][0]=Y[rk*3+1]-Y[rk*3+2]; T[rk][1]=Y[rk*3+0]; T[rk][2]=Y[rk*3+1];
    }
    float Cc[3][3];
#pragma unroll
    for(int kw=0;kw<3;kw++){
      Cc[0][kw]=T[1][kw]-T[2][kw]; Cc[1][kw]=T[0][kw]; Cc[2][kw]=T[1][kw];
    }
    const float* wp = w3 + ((size_t)o*1024+i)*9;
#pragma unroll
    for(int kh=0;kh<3;kh++)
#pragma unroll
      for(int kw=0;kw<3;kw++) acc += wp[kh*3+kw]*Cc[kh][kw];
  }
  acc = warp_sum(acc);
  if(!lane) g_cam3[w] = acc*(1.f/256.f) + g_down4[w];
}

// ---------------- SGz ----------------
__global__ void k_SGz(const float* __restrict__ w2a){
  int w = (blockIdx.x*blockDim.x + threadIdx.x) >> 5;
  int lane = threadIdx.x & 31;
  if(w >= NB*512) return;
  int b = w >> 9, c = w & 511;
  float acc[9];
#pragma unroll
  for(int t=0;t<9;t++) acc[t]=0.f;
  const int map0[3] = {2,4,6};
  const int map1[3] = {6,0,1};
  const int map2[3] = {1,3,5};
  for(int i=lane; i<512; i+=32){
    float CY[49];
    const float* cy = g_CY + ((size_t)b*512+i)*49;
#pragma unroll
    for(int t=0;t<49;t++) CY[t]=cy[t];
    float wv[9];
    const float* wp = w2a + ((size_t)c*512+i)*9;
#pragma unroll
    for(int t=0;t<9;t++) wv[t]=wp[t];
#pragma unroll
    for(int kh=0;kh<3;kh++){
      int rA = (kh==0)?0:((kh==1)?1:2);
#pragma unroll
      for(int kw=0;kw<3;kw++){
        float s=0.f;
#pragma unroll
        for(int ka=0;ka<3;ka++){
          int rc = (rA==0)?map0[ka]:((rA==1)?map1[ka]:map2[ka]);
#pragma unroll
          for(int la=0;la<3;la++){
            int cc = (kw==0)?map0[la]:((kw==1)?map1[la]:map2[la]);
            s += wv[ka*3+la]*CY[rc*7+cc];
          }
        }
        acc[kh*3+kw]+=s;
      }
    }
  }
#pragma unroll
  for(int t=0;t<9;t++) acc[t]=warp_sum(acc[t]);
  if(!lane){
    float* o = g_SGz + (size_t)w*9;
#pragma unroll
    for(int t=0;t<9;t++) o[t]=acc[t];
  }
}

// ---------------- cam2pool ----------------
__global__ void k_cam2(const float* __restrict__ w2b, const float* __restrict__ b2b){
  int w = (blockIdx.x*blockDim.x + threadIdx.x) >> 5;
  int lane = threadIdx.x & 31;
  if(w >= NB*512) return;
  int b = w >> 9, o = w & 511;
  float acc=0.f;
  for(int c=lane; c<512; c+=32){
    const float* wp = w2b + ((size_t)o*512+c)*9;
    const float* sg = g_SGz + ((size_t)b*512+c)*9;
#pragma unroll
    for(int t=0;t<9;t++) acc += wp[t]*sg[t];
  }
  acc = warp_sum(acc);
  if(!lane) g_cam2[w] = acc*(1.f/256.f) + b2b[o] + g_down4[w];
}

// ---------------- final FC ----------------
__global__ void k_out(const float* __restrict__ fcw, const float* __restrict__ fcb,
                      float* __restrict__ out){
  int w = (blockIdx.x*blockDim.x + threadIdx.x) >> 5;
  int lane = threadIdx.x & 31;
  if(w >= NB*2) return;
  int b = w >> 1, j = w & 1;
  float acc=0.f;
  for(int idx=lane; idx<3584; idx+=32){
    float f;
    if(idx<512)       f = g_cam2[b*512+idx];
    else if(idx<1024) f = g_cam3[b*512+idx-512];
    else if(idx<1536) f = g_cam4[b*512+idx-1024];
    else              f = g_sum4[b*2048 + idx-1536]*(1.f/256.f);
    acc += f*fcw[(size_t)j*3584+idx];
  }
  acc = warp_sum(acc);
  if(!lane) out[b*2+j] = acc + fcb[j];
}

// ---------------- launch ----------------
extern "C" void kernel_launch(void* const* d_in, const int* in_sizes, int n_in,
                              void* d_out, int out_size){
  const float* c2  = (const float*)d_in[0];
  const float* c3  = (const float*)d_in[1];
  const float* c4  = (const float*)d_in[2];
  const float* w4  = (const float*)d_in[3];
  const float* b4  = (const float*)d_in[4];
  const float* w3  = (const float*)d_in[5];
  const float* w2a = (const float*)d_in[6];
  const float* w2b = (const float*)d_in[7];
  const float* b2b = (const float*)d_in[8];
  const float* g2  = (const float*)d_in[9];
  const float* g3  = (const float*)d_in[10];
  const float* g4  = (const float*)d_in[11];
  const float* fcw = (const float*)d_in[12];
  const float* fcb = (const float*)d_in[13];
  float* out = (float*)d_out;

  void *pS4, *pM3, *pM2, *pA4, *pA3, *pA2;
  void *pH2,*pL2,*pH3,*pL3,*pH4,*pL4,*pE2;
  void *pP4m,*pP4s,*pP4o,*pP3m,*pP3s,*pP3o;
  cudaGetSymbolAddress(&pS4, g_sum4);
  cudaGetSymbolAddress(&pM3, g_M3);
  cudaGetSymbolAddress(&pM2, g_M2);
  cudaGetSymbolAddress(&pA4, g_A4);
  cudaGetSymbolAddress(&pA3, g_A3);
  cudaGetSymbolAddress(&pA2, g_A2);
  cudaGetSymbolAddress(&pH2, g_h2);
  cudaGetSymbolAddress(&pL2, g_l2);
  cudaGetSymbolAddress(&pH3, g_h3);
  cudaGetSymbolAddress(&pL3, g_l3);
  cudaGetSymbolAddress(&pH4, g_h4);
  cudaGetSymbolAddress(&pL4, g_l4);
  cudaGetSymbolAddress(&pE2, g_E2);
  cudaGetSymbolAddress(&pP4m, g_P4m);
  cudaGetSymbolAddress(&pP4s, g_P4s);
  cudaGetSymbolAddress(&pP4o, g_P4o);
  cudaGetSymbolAddress(&pP3m, g_P3m);
  cudaGetSymbolAddress(&pP3s, g_P3s);
  cudaGetSymbolAddress(&pP3o, g_P3o);

  cudaFuncSetAttribute(k_gram<0>, cudaFuncAttributeMaxDynamicSharedMemorySize, GEMM_SMEM);
  cudaFuncSetAttribute(k_gram<1>, cudaFuncAttributeMaxDynamicSharedMemorySize, GEMM_SMEM);
  cudaFuncSetAttribute(k_gram<9>, cudaFuncAttributeMaxDynamicSharedMemorySize, GEMM_SMEM);
  cudaFuncSetAttribute(k_sm49, cudaFuncAttributeMaxDynamicSharedMemorySize, 512*49*4);

  static cudaStream_t s2 = nullptr, s3 = nullptr;
  static cudaEvent_t evr = nullptr, ev2 = nullptr, ev3 = nullptr;
  if(!s2){
    cudaStreamCreateWithFlags(&s2, cudaStreamNonBlocking);
    cudaStreamCreateWithFlags(&s3, cudaStreamNonBlocking);
    cudaEventCreateWithFlags(&evr, cudaEventDisableTiming);
    cudaEventCreateWithFlags(&ev2, cudaEventDisableTiming);
    cudaEventCreateWithFlags(&ev3, cudaEventDisableTiming);
  }

  // fork
  cudaEventRecord(evr, 0);
  cudaStreamWaitEvent(s2, evr, 0);
  cudaStreamWaitEvent(s3, evr, 0);

  // ---- chain L2 on s3 (longest critical path: enqueue first) ----
  k_split<<<(NB*512*4096/4 + 255)/256, 256, 0, s3>>>(c2, (__half*)pH2, (__half*)pL2, NB*512*4096/4);
  k_gram<0><<<dim3(4*5/2, NB), 256, GEMM_SMEM, s3>>>((__half*)pH2, (__half*)pL2, (float*)pE2, 512, 4096,
      nullptr, nullptr, nullptr, nullptr);
  k_M2<<<NB*512/8, 256, 0, s3>>>(c2);
  k_sm49<<<NB*512/8, 256, 512*49*4, s3>>>((float*)pE2, (float*)pM2, (float*)pA2);

  // ---- chain L3 on s2 (fused K=9) ----
  k_M3<<<NB*1024/8, 256, 0, s2>>>(c3);
  k_split<<<(NB*1024*1024/4 + 255)/256, 256, 0, s2>>>(c3, (__half*)pH3, (__half*)pL3, NB*1024*1024/4);
  k_gram<9><<<dim3(8*9/2, NB), 256, GEMM_SMEM, s2>>>((__half*)pH3, (__half*)pL3, nullptr, 1024, 1024,
      (float*)pM3, (float*)pP3m, (float*)pP3s, (float*)pP3o);
  k_comb<9><<<(NB*1024 + 255)/256, 256, 0, s2>>>((float*)pP3m, (float*)pP3s, (float*)pP3o, (float*)pA3, 1024, 8);

  // ---- chain L4 on default stream (fused K=1) ----
  k_sum4<<<NB*2048/8, 256>>>(c4);
  k_split<<<(NB*2048*256/4 + 255)/256, 256>>>(c4, (__half*)pH4, (__half*)pL4, NB*2048*256/4);
  k_gram<1><<<dim3(16*17/2, NB), 256, GEMM_SMEM>>>((__half*)pH4, (__half*)pL4, nullptr, 2048, 256,
      (float*)pS4, (float*)pP4m, (float*)pP4s, (float*)pP4o);
  k_comb<1><<<(NB*2048 + 255)/256, 256>>>((float*)pP4m, (float*)pP4s, (float*)pP4o, (float*)pA4, 2048, 16);

  // join
  cudaEventRecord(ev2, s2);
  cudaEventRecord(ev3, s3);
  cudaStreamWaitEvent(0, ev2, 0);
  cudaStreamWaitEvent(0, ev3, 0);

  // ---- tail ----
  k_CY  <<<(NB*512+255)/256, 256>>>(g2);
  k_cam4<<<NB*512/8, 256>>>(w4, b4, g4);
  k_cam3<<<NB*512/8, 256>>>(w3, g3);
  k_SGz <<<NB*512/8, 256>>>(w2a);
  k_cam2<<<NB*512/8, 256>>>(w2b, b2b);
  k_out <<<(NB*2*32+255)/256, 256>>>(fcw, fcb, out);
}